// round 2
// baseline (speedup 1.0000x reference)
#include <cuda_runtime.h>

#define NN 50000
#define EE 400000
#define RR 3
#define DD 128
#define HH 8
#define RN (RR*NN)
#define RE (RR*EE)
#define NEG_SLOPE 0.2f
#define LN_EPS 1e-5f

// ---------------- scratch (device globals; no allocs allowed) ----------------
__device__ float g_hp[(size_t)RR*NN*DD];   // projected feats per relation
__device__ float g_el[RN*HH];
__device__ float g_er[RN*HH];
__device__ float g_h1[(size_t)NN*DD];      // layer1 output (relu'd)
__device__ float g_hn[(size_t)NN*DD];      // post-LN features
__device__ float g_tmp[(size_t)NN*DD];     // classifier hidden
__device__ int   g_off[RN+1];
__device__ int   g_cnt[RN];
__device__ int   g_csr[RE];
__device__ int   g_bsum[256];

// ---------------- CSR build ----------------
__global__ void k_zero_cnt() {
    int i = blockIdx.x*blockDim.x + threadIdx.x;
    if (i < RN) g_cnt[i] = 0;
}

__global__ void k_count(const int* __restrict__ edst) {
    int i = blockIdx.x*blockDim.x + threadIdx.x;
    if (i < RE) atomicAdd(&g_cnt[(i/EE)*NN + edst[i]], 1);
}

__device__ __forceinline__ int warp_incl_scan(int v) {
    int lane = threadIdx.x & 31;
    #pragma unroll
    for (int o = 1; o < 32; o <<= 1) {
        int t = __shfl_up_sync(0xffffffffu, v, o);
        if (lane >= o) v += t;
    }
    return v;
}

__global__ void k_scan_local() {   // grid: NB blocks x 1024
    __shared__ int ws[32];
    int i = blockIdx.x*1024 + threadIdx.x;
    int v = (i < RN) ? g_cnt[i] : 0;
    int incl = warp_incl_scan(v);
    int lane = threadIdx.x & 31, w = threadIdx.x >> 5;
    if (lane == 31) ws[w] = incl;
    __syncthreads();
    if (w == 0) {
        int b = ws[lane];
        b = warp_incl_scan(b);
        ws[lane] = b;
    }
    __syncthreads();
    int off = (w > 0) ? ws[w-1] : 0;
    if (i < RN) g_off[i] = off + incl - v;
    if (threadIdx.x == 0) g_bsum[blockIdx.x] = ws[31];
}

__global__ void k_scan_bsum(int nb) {  // 1 block x 256
    __shared__ int ws[8];
    int v = (threadIdx.x < nb) ? g_bsum[threadIdx.x] : 0;
    int incl = warp_incl_scan(v);
    int lane = threadIdx.x & 31, w = threadIdx.x >> 5;
    if (lane == 31) ws[w] = incl;
    __syncthreads();
    if (w == 0) {
        int b = (lane < 8) ? ws[lane] : 0;
        b = warp_incl_scan(b);
        if (lane < 8) ws[lane] = b;
    }
    __syncthreads();
    int off = (w > 0) ? ws[w-1] : 0;
    if (threadIdx.x < nb) g_bsum[threadIdx.x] = off + incl - v;
}

__global__ void k_scan_add() {     // grid: NB blocks x 1024
    int i = blockIdx.x*1024 + threadIdx.x;
    if (i < RN) g_off[i] += g_bsum[blockIdx.x];
    if (i == 0) g_off[RN] = RE;
}

__global__ void k_fill(const int* __restrict__ edst) {
    int i = blockIdx.x*blockDim.x + threadIdx.x;
    if (i < RE) {
        int idx = (i/EE)*NN + edst[i];
        int p = g_off[idx] + atomicAdd(&g_cnt[idx], 1);
        g_csr[p] = i;   // global edge id
    }
}

// ---------------- tiled GEMM: out[r][n][:] = X[n] @ W[r] (+bias, relu) ------
// grid: (ceil(n_rows/64), R'), block 256, dyn smem = (128*128 + 64*132)*4
__global__ void k_gemm128(const float* __restrict__ X, const float* __restrict__ W,
                          const float* __restrict__ bias, float* __restrict__ out,
                          int do_relu, int n_rows)
{
    extern __shared__ float sm[];
    float* Ws = sm;               // [128][128]
    float* Xs = sm + 128*128;     // [64][132]
    const int XS = 132;
    int r = blockIdx.y;
    int n0 = blockIdx.x * 64;
    const float* Wr = W + (size_t)r*128*128;

    for (int i = threadIdx.x; i < 128*32; i += 256)
        ((float4*)Ws)[i] = ((const float4*)Wr)[i];
    for (int i = threadIdx.x; i < 64*32; i += 256) {
        int n = i >> 5, kg = i & 31;
        int gn = n0 + n;
        float4 v = (gn < n_rows) ? ((const float4*)X)[(size_t)gn*32 + kg]
                                 : make_float4(0.f, 0.f, 0.f, 0.f);
        *(float4*)&Xs[n*XS + kg*4] = v;
    }
    __syncthreads();

    int cg = (threadIdx.x & 15) << 3;   // 8 cols
    int ng = (threadIdx.x >> 4) << 2;   // 4 nodes

    unsigned long long acc[4][4];
    #pragma unroll
    for (int a = 0; a < 4; a++)
        #pragma unroll
        for (int b = 0; b < 4; b++) acc[a][b] = 0ull;

    #pragma unroll 4
    for (int k = 0; k < 128; k++) {
        ulonglong2 w01 = *(ulonglong2*)&Ws[k*128 + cg];
        ulonglong2 w23 = *(ulonglong2*)&Ws[k*128 + cg + 4];
        #pragma unroll
        for (int n = 0; n < 4; n++) {
            float xv = Xs[(ng+n)*XS + k];
            unsigned long long xx;
            asm("mov.b64 %0, {%1, %1};" : "=l"(xx) : "f"(xv));
            asm("fma.rn.f32x2 %0, %1, %2, %0;" : "+l"(acc[n][0]) : "l"(xx), "l"(w01.x));
            asm("fma.rn.f32x2 %0, %1, %2, %0;" : "+l"(acc[n][1]) : "l"(xx), "l"(w01.y));
            asm("fma.rn.f32x2 %0, %1, %2, %0;" : "+l"(acc[n][2]) : "l"(xx), "l"(w23.x));
            asm("fma.rn.f32x2 %0, %1, %2, %0;" : "+l"(acc[n][3]) : "l"(xx), "l"(w23.y));
        }
    }

    #pragma unroll
    for (int n = 0; n < 4; n++) {
        int gn = n0 + ng + n;
        if (gn >= n_rows) continue;
        float o[8];
        #pragma unroll
        for (int j = 0; j < 4; j++)
            asm("mov.b64 {%0, %1}, %2;" : "=f"(o[2*j]), "=f"(o[2*j+1]) : "l"(acc[n][j]));
        if (bias) {
            #pragma unroll
            for (int j = 0; j < 8; j++) o[j] += bias[cg+j];
        }
        if (do_relu) {
            #pragma unroll
            for (int j = 0; j < 8; j++) o[j] = fmaxf(o[j], 0.f);
        }
        float* op = out + ((size_t)r*n_rows + gn)*128 + cg;
        *(float4*)&op[0] = make_float4(o[0], o[1], o[2], o[3]);
        *(float4*)&op[4] = make_float4(o[4], o[5], o[6], o[7]);
    }
}

// ---------------- attention coefficients el/er ----------------
__global__ void k_coef(const float* __restrict__ al, const float* __restrict__ ar) {
    int t = blockIdx.x*blockDim.x + threadIdx.x;   // t = r*N + n
    if (t >= RN) return;
    int r = t / NN;
    const float* row = g_hp + (size_t)t*DD;
    #pragma unroll
    for (int h = 0; h < 8; h++) {
        float sl = 0.f, sr = 0.f;
        #pragma unroll
        for (int k4 = 0; k4 < 4; k4++) {
            float4 hv = *(const float4*)&row[h*16 + k4*4];
            float4 a  = *(const float4*)&al[r*128 + h*16 + k4*4];
            float4 b  = *(const float4*)&ar[r*128 + h*16 + k4*4];
            sl += hv.x*a.x + hv.y*a.y + hv.z*a.z + hv.w*a.w;
            sr += hv.x*b.x + hv.y*b.y + hv.z*b.z + hv.w*b.w;
        }
        g_el[t*HH + h] = sl;
        g_er[t*HH + h] = sr;
    }
}

// ---------------- warp-per-node gather softmax-aggregate ----------------
// mode 0: out = relu(agg + bias_sum)          (layer 1 -> g_h1)
// mode 1: out = LN(agg + bias_sum + g_h1)     (layer 2 -> g_hn)
__global__ void k_agg(const int* __restrict__ esrc, const float* __restrict__ bias,
                      const float* __restrict__ lng, const float* __restrict__ lnb,
                      float* __restrict__ out, int mode)
{
    int warp = (blockIdx.x*blockDim.x + threadIdx.x) >> 5;
    if (warp >= NN) return;
    int v = warp;
    int lane = threadIdx.x & 31;
    int h = lane >> 2, q = lane & 3;

    float ax = 0.f, ay = 0.f, az = 0.f, aw = 0.f;

    #pragma unroll
    for (int r = 0; r < RR; r++) {
        int base = r*NN + v;
        int st = g_off[base], en = g_off[base+1];
        int d = en - st;
        if (d == 0) continue;
        float erv = __ldg(&g_er[base*HH + h]);

        // pass 1: per-head max
        float mx = -3.0e38f;
        for (int i = q; i < d; i += 4) {
            int eid = g_csr[st + i];
            int s = __ldg(&esrc[eid]);
            float x = __ldg(&g_el[(r*NN + s)*HH + h]) + erv;
            x = x > 0.f ? x : NEG_SLOPE*x;
            mx = fmaxf(mx, x);
        }
        mx = fmaxf(mx, __shfl_xor_sync(0xffffffffu, mx, 1));
        mx = fmaxf(mx, __shfl_xor_sync(0xffffffffu, mx, 2));

        // pass 2: denom
        float den = 0.f;
        for (int i = q; i < d; i += 4) {
            int eid = g_csr[st + i];
            int s = __ldg(&esrc[eid]);
            float x = __ldg(&g_el[(r*NN + s)*HH + h]) + erv;
            x = x > 0.f ? x : NEG_SLOPE*x;
            den += __expf(x - mx);
        }
        den += __shfl_xor_sync(0xffffffffu, den, 1);
        den += __shfl_xor_sync(0xffffffffu, den, 2);
        float rden = 1.0f / den;

        // pass 3: weighted aggregate (coalesced 512B row gather)
        for (int i = 0; i < d; i++) {
            int eid = g_csr[st + i];
            int s = __ldg(&esrc[eid]);
            float x = __ldg(&g_el[(r*NN + s)*HH + h]) + erv;
            x = x > 0.f ? x : NEG_SLOPE*x;
            float a = __expf(x - mx) * rden;
            float4 hv = *(const float4*)&g_hp[((size_t)r*NN + s)*DD + lane*4];
            ax += a*hv.x; ay += a*hv.y; az += a*hv.z; aw += a*hv.w;
        }
    }

    int c = lane*4;
    ax += bias[c+0] + bias[128+c+0] + bias[256+c+0];
    ay += bias[c+1] + bias[128+c+1] + bias[256+c+1];
    az += bias[c+2] + bias[128+c+2] + bias[256+c+2];
    aw += bias[c+3] + bias[128+c+3] + bias[256+c+3];

    if (mode == 0) {
        float4 o = make_float4(fmaxf(ax,0.f), fmaxf(ay,0.f), fmaxf(az,0.f), fmaxf(aw,0.f));
        *(float4*)&out[(size_t)v*DD + c] = o;
    } else {
        float4 hr = *(const float4*)&g_h1[(size_t)v*DD + c];
        ax += hr.x; ay += hr.y; az += hr.z; aw += hr.w;
        float s  = ax + ay + az + aw;
        float ss = ax*ax + ay*ay + az*az + aw*aw;
        #pragma unroll
        for (int o = 16; o; o >>= 1) {
            s  += __shfl_xor_sync(0xffffffffu, s,  o);
            ss += __shfl_xor_sync(0xffffffffu, ss, o);
        }
        float mu  = s * (1.0f/128.0f);
        float var = ss * (1.0f/128.0f) - mu*mu;
        float inv = rsqrtf(var + LN_EPS);
        float4 o;
        o.x = (ax - mu)*inv*lng[c+0] + lnb[c+0];
        o.y = (ay - mu)*inv*lng[c+1] + lnb[c+1];
        o.z = (az - mu)*inv*lng[c+2] + lnb[c+2];
        o.w = (aw - mu)*inv*lng[c+3] + lnb[c+3];
        *(float4*)&out[(size_t)v*DD + c] = o;
    }
}

// ---------------- classifier final dot: y = tmp @ Wc2 + bc2 ----------------
__global__ void k_cls2(const float* __restrict__ Wc2, const float* __restrict__ bc2,
                       float* __restrict__ out)
{
    int warp = (blockIdx.x*blockDim.x + threadIdx.x) >> 5;
    if (warp >= NN) return;
    int lane = threadIdx.x & 31;
    float4 x = *(const float4*)&g_tmp[(size_t)warp*DD + lane*4];
    float4 w = *(const float4*)&Wc2[lane*4];
    float s = x.x*w.x + x.y*w.y + x.z*w.z + x.w*w.w;
    #pragma unroll
    for (int o = 16; o; o >>= 1) s += __shfl_xor_sync(0xffffffffu, s, o);
    if (lane == 0) out[warp] = s + bc2[0];
}

// ---------------- launch ----------------
extern "C" void kernel_launch(void* const* d_in, const int* in_sizes, int n_in,
                              void* d_out, int out_size)
{
    const float* feat = (const float*)d_in[0];
    const int*   esrc = (const int*)d_in[1];
    const int*   edst = (const int*)d_in[2];
    const float* W1   = (const float*)d_in[3];
    const float* al1  = (const float*)d_in[4];
    const float* ar1  = (const float*)d_in[5];
    const float* b1   = (const float*)d_in[6];
    const float* W2   = (const float*)d_in[7];
    const float* al2  = (const float*)d_in[8];
    const float* ar2  = (const float*)d_in[9];
    const float* b2   = (const float*)d_in[10];
    const float* lng  = (const float*)d_in[11];
    const float* lnb  = (const float*)d_in[12];
    const float* Wc1  = (const float*)d_in[13];
    const float* bc1  = (const float*)d_in[14];
    const float* Wc2  = (const float*)d_in[15];
    const float* bc2  = (const float*)d_in[16];
    float* out = (float*)d_out;

    float *hp, *h1, *hn, *tmp;
    cudaGetSymbolAddress((void**)&hp,  g_hp);
    cudaGetSymbolAddress((void**)&h1,  g_h1);
    cudaGetSymbolAddress((void**)&hn,  g_hn);
    cudaGetSymbolAddress((void**)&tmp, g_tmp);

    const int smem = (128*128 + 64*132) * 4;   // 99328 B
    cudaFuncSetAttribute(k_gemm128, cudaFuncAttributeMaxDynamicSharedMemorySize, smem);

    const int NB = (RN + 1023) / 1024;   // 147

    // --- CSR build ---
    k_zero_cnt<<<(RN+255)/256, 256>>>();
    k_count<<<(RE+255)/256, 256>>>(edst);
    k_scan_local<<<NB, 1024>>>();
    k_scan_bsum<<<1, 256>>>(NB);
    k_scan_add<<<NB, 1024>>>();
    k_zero_cnt<<<(RN+255)/256, 256>>>();
    k_fill<<<(RE+255)/256, 256>>>(edst);

    dim3 gp((NN + 63)/64, RR);
    dim3 g1((NN + 63)/64, 1);
    int aggBlocks = (NN*32 + 255)/256;

    // --- layer 1 ---
    k_gemm128<<<gp, 256, smem>>>(feat, W1, nullptr, hp, 0, NN);
    k_coef<<<(RN+127)/128, 128>>>(al1, ar1);
    k_agg<<<aggBlocks, 256>>>(esrc, b1, nullptr, nullptr, h1, 0);

    // --- layer 2 (+residual+LN fused) ---
    k_gemm128<<<gp, 256, smem>>>(h1, W2, nullptr, hp, 0, NN);
    k_coef<<<(RN+127)/128, 128>>>(al2, ar2);
    k_agg<<<aggBlocks, 256>>>(esrc, b2, lng, lnb, hn, 1);

    // --- classifier ---
    k_gemm128<<<g1, 256, smem>>>(hn, Wc1, bc1, tmp, 1, NN);
    k_cls2<<<aggBlocks, 256>>>(Wc2, bc2, out);
}

// round 3
// speedup vs baseline: 1.4200x; 1.4200x over previous
#include <cuda_runtime.h>

#define NN 50000
#define EE 400000
#define RR 3
#define DD 128
#define HH 8
#define RN (RR*NN)
#define RE (RR*EE)
#define NEG_SLOPE 0.2f
#define LN_EPS 1e-5f

// ---------------- scratch (device globals; no allocs allowed) ----------------
__device__ __align__(128) float g_hp[(size_t)RR*NN*DD];   // projected feats per relation
__device__ __align__(128) float g_el[(size_t)RN*HH];
__device__ __align__(128) float g_er[(size_t)RN*HH];
__device__ __align__(128) float g_h1[(size_t)NN*DD];      // layer1 output (relu'd)
__device__ __align__(128) float g_hn[(size_t)NN*DD];      // post-LN features
__device__ __align__(128) int   g_off[RN+1];
__device__ __align__(128) int   g_cnt[RN];                // counts, then fill cursors
__device__ __align__(128) int   g_csr[RE];
__device__ __align__(128) int   g_bsum[256];

// ---------------- CSR build ----------------
__global__ void k_zero_cnt() {
    int i = blockIdx.x*blockDim.x + threadIdx.x;
    if (i < RN) g_cnt[i] = 0;
}

__global__ void k_count(const int* __restrict__ edst) {
    int i = blockIdx.x*blockDim.x + threadIdx.x;
    if (i < RE) atomicAdd(&g_cnt[(i/EE)*NN + edst[i]], 1);
}

__device__ __forceinline__ int warp_incl_scan(int v) {
    int lane = threadIdx.x & 31;
    #pragma unroll
    for (int o = 1; o < 32; o <<= 1) {
        int t = __shfl_up_sync(0xffffffffu, v, o);
        if (lane >= o) v += t;
    }
    return v;
}

__global__ void k_scan_local() {   // grid: NB x 1024
    __shared__ int ws[32];
    int i = blockIdx.x*1024 + threadIdx.x;
    int v = (i < RN) ? g_cnt[i] : 0;
    int incl = warp_incl_scan(v);
    int lane = threadIdx.x & 31, w = threadIdx.x >> 5;
    if (lane == 31) ws[w] = incl;
    __syncthreads();
    if (w == 0) { int b = ws[lane]; b = warp_incl_scan(b); ws[lane] = b; }
    __syncthreads();
    int off = (w > 0) ? ws[w-1] : 0;
    if (i < RN) g_off[i] = off + incl - v;
    if (threadIdx.x == 0) g_bsum[blockIdx.x] = ws[31];
}

__global__ void k_scan_bsum(int nb) {  // 1 x 256
    __shared__ int ws[8];
    int v = (threadIdx.x < nb) ? g_bsum[threadIdx.x] : 0;
    int incl = warp_incl_scan(v);
    int lane = threadIdx.x & 31, w = threadIdx.x >> 5;
    if (lane == 31) ws[w] = incl;
    __syncthreads();
    if (w == 0) { int b = (lane < 8) ? ws[lane] : 0; b = warp_incl_scan(b); if (lane < 8) ws[lane] = b; }
    __syncthreads();
    int off = (w > 0) ? ws[w-1] : 0;
    if (threadIdx.x < nb) g_bsum[threadIdx.x] = off + incl - v;
}

__global__ void k_scan_add() {     // grid: NB x 1024; also seeds fill cursors
    int i = blockIdx.x*1024 + threadIdx.x;
    if (i < RN) {
        int o = g_off[i] + g_bsum[blockIdx.x];
        g_off[i] = o;
        g_cnt[i] = o;          // fill cursor
    }
    if (i == 0) g_off[RN] = RE;
}

__global__ void k_fill(const int* __restrict__ edst) {
    int i = blockIdx.x*blockDim.x + threadIdx.x;
    if (i < RE) {
        int idx = (i/EE)*NN + edst[i];
        int p = atomicAdd(&g_cnt[idx], 1);
        g_csr[p] = i;   // global edge id
    }
}

// ---------------- 128x128x128 tiled GEMM, 8n x 8c register tile -------------
// MODE 0: projection. out = X @ W[r]; also writes g_el/g_er from al/ar.
// MODE 1: classifier. y = relu(X @ W + bc1) @ Wc2 + bc2 written to out.
// block 256, dyn smem = (64*128 + 128*132)*4 = 100352 B, 2 blocks/SM
template<int MODE>
__global__ void __launch_bounds__(256, 2)
k_gemm(const float* __restrict__ X, const float* __restrict__ W,
       float* __restrict__ outp,
       const float* __restrict__ al, const float* __restrict__ ar,
       const float* __restrict__ bc1, const float* __restrict__ wc2,
       const float* __restrict__ bc2, float* __restrict__ out1,
       int n_rows)
{
    extern __shared__ float sm[];
    float* Ws = sm;                 // [64][128]
    float* Xs = sm + 64*128;        // [128][132] duplicated pairs {x,x}

    const int r  = blockIdx.y;
    const int n0 = blockIdx.x * 128;
    const int tid  = threadIdx.x;
    const int cidx = tid & 15;
    const int nidx = tid >> 4;
    const int cg   = cidx << 3;     // 8 cols
    const float* Wr = W + (size_t)r*128*128;

    unsigned long long acc[8][4];
    #pragma unroll
    for (int j = 0; j < 8; j++)
        #pragma unroll
        for (int b = 0; b < 4; b++) acc[j][b] = 0ull;

    #pragma unroll
    for (int c = 0; c < 2; c++) {
        const int k0 = c*64;
        __syncthreads();
        // W chunk: 64 rows x 128 cols, contiguous
        {
            const float4* src = (const float4*)(Wr + (size_t)k0*128);
            float4* dst = (float4*)Ws;
            for (int i = tid; i < 64*32; i += 256) dst[i] = src[i];
        }
        // X chunk with in-pair duplication
        for (int i = tid; i < 128*16; i += 256) {
            int n = i >> 4, kg = i & 15;
            int gn = n0 + n;
            float4 v = (gn < n_rows) ? *(const float4*)&X[(size_t)gn*128 + k0 + kg*4]
                                     : make_float4(0.f,0.f,0.f,0.f);
            float* d = Xs + n*132 + kg*8;
            *(float4*)d       = make_float4(v.x, v.x, v.y, v.y);
            *(float4*)(d + 4) = make_float4(v.z, v.z, v.w, v.w);
        }
        __syncthreads();

        const float* xb = Xs + (nidx*8)*132;
        #pragma unroll 2
        for (int kk = 0; kk < 64; kk++) {
            ulonglong2 w01 = *(const ulonglong2*)&Ws[kk*128 + cg];
            ulonglong2 w23 = *(const ulonglong2*)&Ws[kk*128 + cg + 4];
            #pragma unroll
            for (int j = 0; j < 8; j++) {
                unsigned long long xx = *(const unsigned long long*)(xb + j*132 + 2*kk);
                asm("fma.rn.f32x2 %0, %1, %2, %0;" : "+l"(acc[j][0]) : "l"(xx), "l"(w01.x));
                asm("fma.rn.f32x2 %0, %1, %2, %0;" : "+l"(acc[j][1]) : "l"(xx), "l"(w01.y));
                asm("fma.rn.f32x2 %0, %1, %2, %0;" : "+l"(acc[j][2]) : "l"(xx), "l"(w23.x));
                asm("fma.rn.f32x2 %0, %1, %2, %0;" : "+l"(acc[j][3]) : "l"(xx), "l"(w23.y));
            }
        }
    }

    // epilogue parameter vectors for this thread's 8 columns
    float p0[8], p1[8];
    if (MODE == 0) {
        #pragma unroll
        for (int t = 0; t < 8; t++) { p0[t] = al[r*128 + cg + t]; p1[t] = ar[r*128 + cg + t]; }
    } else {
        #pragma unroll
        for (int t = 0; t < 8; t++) { p0[t] = bc1[cg + t]; p1[t] = wc2[cg + t]; }
    }

    #pragma unroll
    for (int j = 0; j < 8; j++) {
        int gn = n0 + nidx*8 + j;
        bool ok = gn < n_rows;
        float o[8];
        #pragma unroll
        for (int b = 0; b < 4; b++)
            asm("mov.b64 {%0, %1}, %2;" : "=f"(o[2*b]), "=f"(o[2*b+1]) : "l"(acc[j][b]));

        if (MODE == 0) {
            if (ok) {
                float* op = outp + ((size_t)r*n_rows + gn)*128 + cg;
                *(float4*)&op[0] = make_float4(o[0], o[1], o[2], o[3]);
                *(float4*)&op[4] = make_float4(o[4], o[5], o[6], o[7]);
            }
            float el = 0.f, er = 0.f;
            #pragma unroll
            for (int t = 0; t < 8; t++) { el += o[t]*p0[t]; er += o[t]*p1[t]; }
            el += __shfl_xor_sync(0xffffffffu, el, 1);
            er += __shfl_xor_sync(0xffffffffu, er, 1);
            if (ok && !(tid & 1)) {
                int head = cidx >> 1;
                g_el[((size_t)r*NN + gn)*HH + head] = el;
                g_er[((size_t)r*NN + gn)*HH + head] = er;
            }
        } else {
            float s = 0.f;
            #pragma unroll
            for (int t = 0; t < 8; t++) {
                float hv = fmaxf(o[t] + p0[t], 0.f);
                s += hv * p1[t];
            }
            s += __shfl_xor_sync(0xffffffffu, s, 1);
            s += __shfl_xor_sync(0xffffffffu, s, 2);
            s += __shfl_xor_sync(0xffffffffu, s, 4);
            s += __shfl_xor_sync(0xffffffffu, s, 8);
            if (ok && cidx == 0) out1[gn] = s + bc2[0];
        }
    }
}

// ---------------- warp-per-node single-pass softmax-aggregate ----------------
// Softmax is shift-invariant; |el+er| is O(1) here so exp is computed unshifted
// and normalization folded into the epilogue: sum(alpha*h) = sum(e*h)/sum(e).
// mode 0: out = relu(agg + bias_sum)          (layer 1 -> g_h1)
// mode 1: out = LN(agg + bias_sum + g_h1)     (layer 2 -> g_hn)
__global__ void k_agg(const int* __restrict__ esrc, const float* __restrict__ bias,
                      const float* __restrict__ lng, const float* __restrict__ lnb,
                      float* __restrict__ out, int mode)
{
    int warp = (blockIdx.x*blockDim.x + threadIdx.x) >> 5;
    if (warp >= NN) return;
    int v = warp;
    int lane = threadIdx.x & 31;
    int h = lane >> 2;

    float ax = 0.f, ay = 0.f, az = 0.f, aw = 0.f;

    #pragma unroll
    for (int r = 0; r < RR; r++) {
        int base = r*NN + v;
        int st = g_off[base], d = g_off[base+1] - st;
        if (d == 0) continue;
        float erv = __ldg(&g_er[(size_t)base*HH + h]);

        float nx = 0.f, ny = 0.f, nz = 0.f, nw = 0.f, den = 0.f;
        int s_next = __ldg(&esrc[__ldg(&g_csr[st])]);
        for (int i = 0; i < d; i++) {
            int s = s_next;
            if (i + 1 < d) s_next = __ldg(&esrc[__ldg(&g_csr[st + i + 1])]);
            float x = __ldg(&g_el[(size_t)(r*NN + s)*HH + h]) + erv;
            x = x > 0.f ? x : NEG_SLOPE*x;
            float e = __expf(x);
            den += e;
            float4 hv = *(const float4*)&g_hp[((size_t)r*NN + s)*DD + lane*4];
            nx += e*hv.x; ny += e*hv.y; nz += e*hv.z; nw += e*hv.w;
        }
        float rd = 1.0f / den;      // identical across the 4 lanes of a head
        ax += nx*rd; ay += ny*rd; az += nz*rd; aw += nw*rd;
    }

    int c = lane*4;
    ax += bias[c+0] + bias[128+c+0] + bias[256+c+0];
    ay += bias[c+1] + bias[128+c+1] + bias[256+c+1];
    az += bias[c+2] + bias[128+c+2] + bias[256+c+2];
    aw += bias[c+3] + bias[128+c+3] + bias[256+c+3];

    if (mode == 0) {
        float4 o = make_float4(fmaxf(ax,0.f), fmaxf(ay,0.f), fmaxf(az,0.f), fmaxf(aw,0.f));
        *(float4*)&out[(size_t)v*DD + c] = o;
    } else {
        float4 hr = *(const float4*)&g_h1[(size_t)v*DD + c];
        ax += hr.x; ay += hr.y; az += hr.z; aw += hr.w;
        float s  = ax + ay + az + aw;
        float ss = ax*ax + ay*ay + az*az + aw*aw;
        #pragma unroll
        for (int o = 16; o; o >>= 1) {
            s  += __shfl_xor_sync(0xffffffffu, s,  o);
            ss += __shfl_xor_sync(0xffffffffu, ss, o);
        }
        float mu  = s * (1.0f/128.0f);
        float var = ss * (1.0f/128.0f) - mu*mu;
        float inv = rsqrtf(var + LN_EPS);
        float4 o;
        o.x = (ax - mu)*inv*lng[c+0] + lnb[c+0];
        o.y = (ay - mu)*inv*lng[c+1] + lnb[c+1];
        o.z = (az - mu)*inv*lng[c+2] + lnb[c+2];
        o.w = (aw - mu)*inv*lng[c+3] + lnb[c+3];
        *(float4*)&out[(size_t)v*DD + c] = o;
    }
}

// ---------------- launch ----------------
extern "C" void kernel_launch(void* const* d_in, const int* in_sizes, int n_in,
                              void* d_out, int out_size)
{
    const float* feat = (const float*)d_in[0];
    const int*   esrc = (const int*)d_in[1];
    const int*   edst = (const int*)d_in[2];
    const float* W1   = (const float*)d_in[3];
    const float* al1  = (const float*)d_in[4];
    const float* ar1  = (const float*)d_in[5];
    const float* b1   = (const float*)d_in[6];
    const float* W2   = (const float*)d_in[7];
    const float* al2  = (const float*)d_in[8];
    const float* ar2  = (const float*)d_in[9];
    const float* b2   = (const float*)d_in[10];
    const float* lng  = (const float*)d_in[11];
    const float* lnb  = (const float*)d_in[12];
    const float* Wc1  = (const float*)d_in[13];
    const float* bc1  = (const float*)d_in[14];
    const float* Wc2  = (const float*)d_in[15];
    const float* bc2  = (const float*)d_in[16];
    float* out = (float*)d_out;

    float *hp, *h1, *hn;
    cudaGetSymbolAddress((void**)&hp, g_hp);
    cudaGetSymbolAddress((void**)&h1, g_h1);
    cudaGetSymbolAddress((void**)&hn, g_hn);

    const int smem = (64*128 + 128*132) * 4;   // 100352 B
    cudaFuncSetAttribute(k_gemm<0>, cudaFuncAttributeMaxDynamicSharedMemorySize, smem);
    cudaFuncSetAttribute(k_gemm<1>, cudaFuncAttributeMaxDynamicSharedMemorySize, smem);

    const int NB = (RN + 1023) / 1024;   // 147

    // --- CSR build (6 launches) ---
    k_zero_cnt<<<(RN+255)/256, 256>>>();
    k_count<<<(RE+255)/256, 256>>>(edst);
    k_scan_local<<<NB, 1024>>>();
    k_scan_bsum<<<1, 256>>>(NB);
    k_scan_add<<<NB, 1024>>>();
    k_fill<<<(RE+255)/256, 256>>>(edst);

    dim3 gp((NN + 127)/128, RR);
    dim3 g1((NN + 127)/128, 1);
    int aggBlocks = (NN*32 + 255)/256;

    // --- layer 1 ---
    k_gemm<0><<<gp, 256, smem>>>(feat, W1, hp, al1, ar1, nullptr, nullptr, nullptr, nullptr, NN);
    k_agg<<<aggBlocks, 256>>>(esrc, b1, nullptr, nullptr, h1, 0);

    // --- layer 2 (+residual+LN fused) ---
    k_gemm<0><<<gp, 256, smem>>>(h1, W2, hp, al2, ar2, nullptr, nullptr, nullptr, nullptr, NN);
    k_agg<<<aggBlocks, 256>>>(esrc, b2, lng, lnb, hn, 1);

    // --- classifier (hidden GEMM + relu + final dot fused) ---
    k_gemm<1><<<g1, 256, smem>>>(hn, Wc1, nullptr, nullptr, nullptr, bc1, Wc2, bc2, out, NN);
}

// round 5
// speedup vs baseline: 2.2286x; 1.5695x over previous
#include <cuda_runtime.h>
#include <cuda_bf16.h>
#include <cstdint>

#define NN 50000
#define EE 400000
#define RR 3
#define DD 128
#define HH 8
#define RN (RR*NN)
#define RE (RR*EE)
#define NEG_SLOPE 0.2f
#define LN_EPS 1e-5f

// ---------------- scratch (device globals; no allocs allowed) ----------------
__device__ __align__(128) float g_hp[(size_t)RR*NN*DD];
__device__ __align__(128) float g_el[(size_t)RN*HH];
__device__ __align__(128) float g_er[(size_t)RN*HH];
__device__ __align__(128) float g_h1[(size_t)NN*DD];
__device__ __align__(128) float g_hn[(size_t)NN*DD];
__device__ __align__(128) int   g_off[RN+1];
__device__ __align__(128) int   g_cnt[RN];
__device__ __align__(128) int   g_csr[RE];
__device__ __align__(128) int   g_bsum[256];
// pre-split transposed weights, 7 slots: W1 r0-2, W2 r0-2, Wc1. layout [slot][n][k]
__device__ __align__(128) __nv_bfloat16 g_wh[7*128*128];
__device__ __align__(128) __nv_bfloat16 g_wl[7*128*128];

__device__ __forceinline__ uint32_t smem_u32(const void* p) {
    uint32_t a;
    asm("{ .reg .u64 t; cvta.to.shared.u64 t, %1; cvt.u32.u64 %0, t; }" : "=r"(a) : "l"(p));
    return a;
}

#define LDSM4(R, A) \
    asm volatile("ldmatrix.sync.aligned.m8n8.x4.shared.b16 {%0,%1,%2,%3}, [%4];" \
        : "=r"((R)[0]), "=r"((R)[1]), "=r"((R)[2]), "=r"((R)[3]) : "r"(A))

#define MMA(C, A, B0, B1) \
    asm volatile("mma.sync.aligned.m16n8k16.row.col.f32.bf16.bf16.f32 " \
        "{%0,%1,%2,%3}, {%4,%5,%6,%7}, {%8,%9}, {%0,%1,%2,%3};" \
        : "+f"((C)[0]), "+f"((C)[1]), "+f"((C)[2]), "+f"((C)[3]) \
        : "r"((A)[0]), "r"((A)[1]), "r"((A)[2]), "r"((A)[3]), "r"(B0), "r"(B1))

// ---------------- weight setup: split fp32 -> bf16 hi/lo, transpose ----------
__global__ void k_wsetup(const float* __restrict__ W1, const float* __restrict__ W2,
                         const float* __restrict__ Wc1)
{
    int i = blockIdx.x*blockDim.x + threadIdx.x;
    if (i >= 7*128*128) return;
    int slot = i >> 14, rem = i & 16383;
    int n = rem >> 7, k = rem & 127;
    float w;
    if (slot < 3)      w = W1[slot*16384 + k*128 + n];
    else if (slot < 6) w = W2[(slot-3)*16384 + k*128 + n];
    else               w = Wc1[k*128 + n];
    __nv_bfloat16 hi = __float2bfloat16(w);
    __nv_bfloat16 lo = __float2bfloat16(w - __bfloat162float(hi));
    g_wh[i] = hi;
    g_wl[i] = lo;
}

// ---------------- CSR build ----------------
__global__ void k_zero_cnt() {
    int i = blockIdx.x*blockDim.x + threadIdx.x;
    if (i < RN) g_cnt[i] = 0;
}
__global__ void k_count(const int* __restrict__ edst) {
    int i = blockIdx.x*blockDim.x + threadIdx.x;
    if (i < RE) atomicAdd(&g_cnt[(i/EE)*NN + edst[i]], 1);
}
__device__ __forceinline__ int warp_incl_scan(int v) {
    int lane = threadIdx.x & 31;
    #pragma unroll
    for (int o = 1; o < 32; o <<= 1) {
        int t = __shfl_up_sync(0xffffffffu, v, o);
        if (lane >= o) v += t;
    }
    return v;
}
__global__ void k_scan_local() {
    __shared__ int ws[32];
    int i = blockIdx.x*1024 + threadIdx.x;
    int v = (i < RN) ? g_cnt[i] : 0;
    int incl = warp_incl_scan(v);
    int lane = threadIdx.x & 31, w = threadIdx.x >> 5;
    if (lane == 31) ws[w] = incl;
    __syncthreads();
    if (w == 0) { int b = ws[lane]; b = warp_incl_scan(b); ws[lane] = b; }
    __syncthreads();
    int off = (w > 0) ? ws[w-1] : 0;
    if (i < RN) g_off[i] = off + incl - v;
    if (threadIdx.x == 0) g_bsum[blockIdx.x] = ws[31];
}
__global__ void k_scan_bsum(int nb) {
    __shared__ int ws[8];
    int v = (threadIdx.x < nb) ? g_bsum[threadIdx.x] : 0;
    int incl = warp_incl_scan(v);
    int lane = threadIdx.x & 31, w = threadIdx.x >> 5;
    if (lane == 31) ws[w] = incl;
    __syncthreads();
    if (w == 0) { int b = (lane < 8) ? ws[lane] : 0; b = warp_incl_scan(b); if (lane < 8) ws[lane] = b; }
    __syncthreads();
    int off = (w > 0) ? ws[w-1] : 0;
    if (threadIdx.x < nb) g_bsum[threadIdx.x] = off + incl - v;
}
__global__ void k_scan_add() {
    int i = blockIdx.x*1024 + threadIdx.x;
    if (i < RN) {
        int o = g_off[i] + g_bsum[blockIdx.x];
        g_off[i] = o;
        g_cnt[i] = o;
    }
    if (i == 0) g_off[RN] = RE;
}
__global__ void k_fill(const int* __restrict__ edst) {
    int i = blockIdx.x*blockDim.x + threadIdx.x;
    if (i < RE) {
        int idx = (i/EE)*NN + edst[i];
        int p = atomicAdd(&g_cnt[idx], 1);
        g_csr[p] = i;
    }
}

// ---------------- HMMA split-bf16 GEMM, 128x128 tile, K chunked by 64 --------
// MODE 0: g_hp[r] rows = X @ W[slot]; also g_el/g_er from al/ar.
// MODE 1: out1[m] = relu(X@W + bc1) . wc2 + bc2
// block 256 (8 warps: 4 along M x 2 along N), warp tile 32x64.
#define ASTR 72
#define SM_BF  (4*128*ASTR)                 // 4 bf16 tiles
#define SM_TOT (SM_BF*2 + 256*4 + 256*4)    // tiles + params + partials

template<int MODE>
__global__ void __launch_bounds__(256, 2)
k_tgemm(const float* __restrict__ X, int slot0,
        const float* __restrict__ al, const float* __restrict__ ar,
        const float* __restrict__ bc1, const float* __restrict__ wc2,
        const float* __restrict__ bc2, float* __restrict__ out1)
{
    extern __shared__ char smem[];
    __nv_bfloat16* Ah = (__nv_bfloat16*)smem;       // [128][72]
    __nv_bfloat16* Av = Ah + 128*ASTR;
    __nv_bfloat16* Bh = Av + 128*ASTR;
    __nv_bfloat16* Bv = Bh + 128*ASTR;
    float* Ps = (float*)(Bv + 128*ASTR);            // 256 param floats
    float* Pt = Ps + 256;                           // 128x2 row partials (mode1)

    const int tid  = threadIdx.x;
    const int lane = tid & 31;
    const int w    = tid >> 5;
    const int wm   = w & 3;          // 0..3 along M
    const int wn   = w >> 2;         // 0..1 along N
    const int r    = blockIdx.y;
    const int slot = slot0 + r;
    const int n0   = blockIdx.x * 128;

    // stage epilogue params
    if (MODE == 0) Ps[tid] = (tid < 128) ? al[r*128 + tid] : ar[r*128 + tid - 128];
    else           Ps[tid] = (tid < 128) ? bc1[tid]        : wc2[tid - 128];

    const __nv_bfloat16* wh = g_wh + (size_t)slot*16384;
    const __nv_bfloat16* wl = g_wl + (size_t)slot*16384;

    const uint32_t sAh = smem_u32(Ah), sAv = smem_u32(Av);
    const uint32_t sBh = smem_u32(Bh), sBv = smem_u32(Bv);
    // ldmatrix lane address offsets (bytes)
    const uint32_t aOff = ((wm*32 + (lane & 15))*ASTR + (lane >> 4)*8) * 2;
    const uint32_t bOff = ((wn*64 + ((lane >> 4) & 1)*8 + (lane & 7))*ASTR
                           + ((lane >> 3) & 1)*8) * 2;

    float acc[2][8][4];
    #pragma unroll
    for (int mt = 0; mt < 2; mt++)
        #pragma unroll
        for (int nt = 0; nt < 8; nt++)
            #pragma unroll
            for (int q = 0; q < 4; q++) acc[mt][nt][q] = 0.f;

    #pragma unroll
    for (int ch = 0; ch < 2; ch++) {
        __syncthreads();
        // B: 128 n-rows x 64 k, both splits
        #pragma unroll
        for (int i = 0; i < 4; i++) {
            int idx = tid + i*256;
            int n = idx >> 3, k = (idx & 7) << 3;
            *(uint4*)&Bh[n*ASTR + k] = *(const uint4*)&wh[n*128 + ch*64 + k];
            *(uint4*)&Bv[n*ASTR + k] = *(const uint4*)&wl[n*128 + ch*64 + k];
        }
        // A: 128 m-rows x 64 k fp32, split to hi/lo
        #pragma unroll
        for (int i = 0; i < 4; i++) {
            int idx = tid + i*256;
            int m = idx >> 3, k = (idx & 7) << 3;
            int gm = n0 + m;
            float v[8] = {0.f,0.f,0.f,0.f,0.f,0.f,0.f,0.f};
            if (gm < NN) {
                const float* xp = X + (size_t)gm*128 + ch*64 + k;
                float4 x0 = *(const float4*)xp;
                float4 x1 = *(const float4*)(xp + 4);
                v[0]=x0.x; v[1]=x0.y; v[2]=x0.z; v[3]=x0.w;
                v[4]=x1.x; v[5]=x1.y; v[6]=x1.z; v[7]=x1.w;
            }
            __nv_bfloat16 hh[8], ll[8];
            #pragma unroll
            for (int t = 0; t < 8; t++) {
                hh[t] = __float2bfloat16(v[t]);
                ll[t] = __float2bfloat16(v[t] - __bfloat162float(hh[t]));
            }
            *(uint4*)&Ah[m*ASTR + k] = *(const uint4*)hh;
            *(uint4*)&Av[m*ASTR + k] = *(const uint4*)ll;
        }
        __syncthreads();

        #pragma unroll
        for (int ks = 0; ks < 4; ks++) {
            uint32_t ah[2][4], av[2][4];
            #pragma unroll
            for (int mt = 0; mt < 2; mt++) {
                LDSM4(ah[mt], sAh + aOff + mt*(16*ASTR*2) + ks*32);
                LDSM4(av[mt], sAv + aOff + mt*(16*ASTR*2) + ks*32);
            }
            #pragma unroll
            for (int p = 0; p < 4; p++) {      // nt pairs
                uint32_t bh[4], bv[4];
                LDSM4(bh, sBh + bOff + p*(16*ASTR*2) + ks*32);
                LDSM4(bv, sBv + bOff + p*(16*ASTR*2) + ks*32);
                #pragma unroll
                for (int mt = 0; mt < 2; mt++) {
                    MMA(acc[mt][2*p],   ah[mt], bh[0], bh[1]);
                    MMA(acc[mt][2*p],   ah[mt], bv[0], bv[1]);
                    MMA(acc[mt][2*p],   av[mt], bh[0], bh[1]);
                    MMA(acc[mt][2*p+1], ah[mt], bh[2], bh[3]);
                    MMA(acc[mt][2*p+1], ah[mt], bv[2], bv[3]);
                    MMA(acc[mt][2*p+1], av[mt], bh[2], bh[3]);
                }
            }
        }
    }

    // ---- epilogue ----
    const int g  = lane >> 2;        // fragment row within 8
    const int c2 = (lane & 3) * 2;   // fragment col pair

    if (MODE == 0) {
        #pragma unroll
        for (int mt = 0; mt < 2; mt++) {
            #pragma unroll
            for (int rh = 0; rh < 2; rh++) {
                int gm = n0 + wm*32 + mt*16 + rh*8 + g;
                bool ok = gm < NN;
                if (ok) {
                    float* op = g_hp + ((size_t)r*NN + gm)*128;
                    #pragma unroll
                    for (int nt = 0; nt < 8; nt++) {
                        int n = wn*64 + nt*8 + c2;
                        *(float2*)&op[n] = make_float2(acc[mt][nt][rh*2], acc[mt][nt][rh*2+1]);
                    }
                }
                #pragma unroll
                for (int j = 0; j < 4; j++) {   // local heads
                    float el = 0.f, er = 0.f;
                    #pragma unroll
                    for (int t = 0; t < 2; t++) {
                        int nt = 2*j + t;
                        int n = wn*64 + nt*8 + c2;
                        float v0 = acc[mt][nt][rh*2], v1 = acc[mt][nt][rh*2+1];
                        el += v0*Ps[n] + v1*Ps[n+1];
                        er += v0*Ps[128+n] + v1*Ps[128+n+1];
                    }
                    el += __shfl_xor_sync(0xffffffffu, el, 1);
                    er += __shfl_xor_sync(0xffffffffu, er, 1);
                    el += __shfl_xor_sync(0xffffffffu, el, 2);
                    er += __shfl_xor_sync(0xffffffffu, er, 2);
                    if ((lane & 3) == 0 && ok) {
                        g_el[((size_t)r*NN + gm)*HH + wn*4 + j] = el;
                        g_er[((size_t)r*NN + gm)*HH + wn*4 + j] = er;
                    }
                }
            }
        }
    } else {
        #pragma unroll
        for (int mt = 0; mt < 2; mt++) {
            #pragma unroll
            for (int rh = 0; rh < 2; rh++) {
                float s = 0.f;
                #pragma unroll
                for (int nt = 0; nt < 8; nt++) {
                    int n = wn*64 + nt*8 + c2;
                    s += fmaxf(acc[mt][nt][rh*2]   + Ps[n],   0.f) * Ps[128+n];
                    s += fmaxf(acc[mt][nt][rh*2+1] + Ps[n+1], 0.f) * Ps[128+n+1];
                }
                s += __shfl_xor_sync(0xffffffffu, s, 1);
                s += __shfl_xor_sync(0xffffffffu, s, 2);
                if ((lane & 3) == 0)
                    Pt[(wm*32 + mt*16 + rh*8 + g)*2 + wn] = s;
            }
        }
        __syncthreads();
        if (tid < 128) {
            int gm = n0 + tid;
            if (gm < NN) out1[gm] = Pt[tid*2] + Pt[tid*2+1] + bc2[0];
        }
    }
}

// ---------------- warp-per-node single-pass softmax-aggregate ----------------
__global__ void k_agg(const int* __restrict__ esrc, const float* __restrict__ bias,
                      const float* __restrict__ lng, const float* __restrict__ lnb,
                      float* __restrict__ out, int mode)
{
    int warp = (blockIdx.x*blockDim.x + threadIdx.x) >> 5;
    if (warp >= NN) return;
    int v = warp;
    int lane = threadIdx.x & 31;
    int h = lane >> 2;

    float ax = 0.f, ay = 0.f, az = 0.f, aw = 0.f;

    #pragma unroll
    for (int r = 0; r < RR; r++) {
        int base = r*NN + v;
        int st = g_off[base], d = g_off[base+1] - st;
        if (d == 0) continue;
        float erv = __ldg(&g_er[(size_t)base*HH + h]);

        float nx = 0.f, ny = 0.f, nz = 0.f, nw = 0.f, den = 0.f;
        int s_next = __ldg(&esrc[__ldg(&g_csr[st])]);
        for (int i = 0; i < d; i++) {
            int s = s_next;
            if (i + 1 < d) s_next = __ldg(&esrc[__ldg(&g_csr[st + i + 1])]);
            float x = __ldg(&g_el[(size_t)(r*NN + s)*HH + h]) + erv;
            x = x > 0.f ? x : NEG_SLOPE*x;
            float e = __expf(x);
            den += e;
            float4 hv = *(const float4*)&g_hp[((size_t)r*NN + s)*DD + lane*4];
            nx += e*hv.x; ny += e*hv.y; nz += e*hv.z; nw += e*hv.w;
        }
        float rd = 1.0f / den;
        ax += nx*rd; ay += ny*rd; az += nz*rd; aw += nw*rd;
    }

    int c = lane*4;
    ax += bias[c+0] + bias[128+c+0] + bias[256+c+0];
    ay += bias[c+1] + bias[128+c+1] + bias[256+c+1];
    az += bias[c+2] + bias[128+c+2] + bias[256+c+2];
    aw += bias[c+3] + bias[128+c+3] + bias[256+c+3];

    if (mode == 0) {
        float4 o = make_float4(fmaxf(ax,0.f), fmaxf(ay,0.f), fmaxf(az,0.f), fmaxf(aw,0.f));
        *(float4*)&out[(size_t)v*DD + c] = o;
    } else {
        float4 hr = *(const float4*)&g_h1[(size_t)v*DD + c];
        ax += hr.x; ay += hr.y; az += hr.z; aw += hr.w;
        float s  = ax + ay + az + aw;
        float ss = ax*ax + ay*ay + az*az + aw*aw;
        #pragma unroll
        for (int o = 16; o; o >>= 1) {
            s  += __shfl_xor_sync(0xffffffffu, s,  o);
            ss += __shfl_xor_sync(0xffffffffu, ss, o);
        }
        float mu  = s * (1.0f/128.0f);
        float var = ss * (1.0f/128.0f) - mu*mu;
        float inv = rsqrtf(var + LN_EPS);
        float4 o;
        o.x = (ax - mu)*inv*lng[c+0] + lnb[c+0];
        o.y = (ay - mu)*inv*lng[c+1] + lnb[c+1];
        o.z = (az - mu)*inv*lng[c+2] + lnb[c+2];
        o.w = (aw - mu)*inv*lng[c+3] + lnb[c+3];
        *(float4*)&out[(size_t)v*DD + c] = o;
    }
}

// ---------------- launch ----------------
extern "C" void kernel_launch(void* const* d_in, const int* in_sizes, int n_in,
                              void* d_out, int out_size)
{
    const float* feat = (const float*)d_in[0];
    const int*   esrc = (const int*)d_in[1];
    const int*   edst = (const int*)d_in[2];
    const float* W1   = (const float*)d_in[3];
    const float* al1  = (const float*)d_in[4];
    const float* ar1  = (const float*)d_in[5];
    const float* b1   = (const float*)d_in[6];
    const float* W2   = (const float*)d_in[7];
    const float* al2  = (const float*)d_in[8];
    const float* ar2  = (const float*)d_in[9];
    const float* b2   = (const float*)d_in[10];
    const float* lng  = (const float*)d_in[11];
    const float* lnb  = (const float*)d_in[12];
    const float* Wc1  = (const float*)d_in[13];
    const float* bc1  = (const float*)d_in[14];
    const float* Wc2  = (const float*)d_in[15];
    const float* bc2  = (const float*)d_in[16];
    float* out = (float*)d_out;

    float *h1, *hn;
    cudaGetSymbolAddress((void**)&h1, g_h1);
    cudaGetSymbolAddress((void**)&hn, g_hn);

    cudaFuncSetAttribute(k_tgemm<0>, cudaFuncAttributeMaxDynamicSharedMemorySize, SM_TOT);
    cudaFuncSetAttribute(k_tgemm<1>, cudaFuncAttributeMaxDynamicSharedMemorySize, SM_TOT);

    const int NB = (RN + 1023) / 1024;
    dim3 gp((NN + 127)/128, RR);
    dim3 g1((NN + 127)/128, 1);
    int aggBlocks = (NN*32 + 255)/256;

    // order chosen so launch #6 (ncu -s 5 -c 1) is the layer-1 GEMM
    k_zero_cnt<<<(RN+255)/256, 256>>>();                                   // 1
    k_count<<<(RE+255)/256, 256>>>(edst);                                  // 2
    k_scan_local<<<NB, 1024>>>();                                          // 3
    k_scan_bsum<<<1, 256>>>(NB);                                           // 4
    k_wsetup<<<(7*16384 + 255)/256, 256>>>(W1, W2, Wc1);                   // 5
    k_tgemm<0><<<gp, 256, SM_TOT>>>(feat, 0, al1, ar1, 0, 0, 0, 0);        // 6
    k_scan_add<<<NB, 1024>>>();                                            // 7
    k_fill<<<(RE+255)/256, 256>>>(edst);                                   // 8

    k_agg<<<aggBlocks, 256>>>(esrc, b1, nullptr, nullptr, h1, 0);          // 9
    k_tgemm<0><<<gp, 256, SM_TOT>>>(h1, 3, al2, ar2, 0, 0, 0, 0);          // 10
    k_agg<<<aggBlocks, 256>>>(esrc, b2, lng, lnb, hn, 1);                  // 11
    k_tgemm<1><<<g1, 256, SM_TOT>>>(hn, 6, 0, 0, bc1, Wc2, bc2, out);      // 12
}

// round 6
// speedup vs baseline: 2.5165x; 1.1292x over previous
#include <cuda_runtime.h>
#include <cuda_bf16.h>
#include <cuda_fp16.h>
#include <cstdint>

#define NN 50000
#define EE 400000
#define RR 3
#define DD 128
#define HH 8
#define RN (RR*NN)
#define RE (RR*EE)
#define NEG_SLOPE 0.2f
#define LN_EPS 1e-5f

// ---------------- scratch (device globals; no allocs allowed) ----------------
__device__ __align__(128) __half g_hp[(size_t)RR*NN*DD];   // fp16: gather traffic halved
__device__ __align__(128) float g_el[(size_t)RN*HH];
__device__ __align__(128) float g_er[(size_t)RN*HH];
__device__ __align__(128) float g_h1[(size_t)NN*DD];
__device__ __align__(128) float g_hn[(size_t)NN*DD];
__device__ __align__(128) int   g_off[RN+1];
__device__ __align__(128) int   g_cnt[RN];
__device__ __align__(128) int   g_csr[RE];
__device__ __align__(128) int   g_bsum[256];
// pre-split transposed weights, 7 slots: W1 r0-2, W2 r0-2, Wc1. layout [slot][n][k]
__device__ __align__(128) __nv_bfloat16 g_wh[7*128*128];
__device__ __align__(128) __nv_bfloat16 g_wl[7*128*128];

__device__ __forceinline__ uint32_t smem_u32(const void* p) {
    uint32_t a;
    asm("{ .reg .u64 t; cvta.to.shared.u64 t, %1; cvt.u32.u64 %0, t; }" : "=r"(a) : "l"(p));
    return a;
}

#define LDSM4(R, A) \
    asm volatile("ldmatrix.sync.aligned.m8n8.x4.shared.b16 {%0,%1,%2,%3}, [%4];" \
        : "=r"((R)[0]), "=r"((R)[1]), "=r"((R)[2]), "=r"((R)[3]) : "r"(A))

#define MMA(C, A, B0, B1) \
    asm volatile("mma.sync.aligned.m16n8k16.row.col.f32.bf16.bf16.f32 " \
        "{%0,%1,%2,%3}, {%4,%5,%6,%7}, {%8,%9}, {%0,%1,%2,%3};" \
        : "+f"((C)[0]), "+f"((C)[1]), "+f"((C)[2]), "+f"((C)[3]) \
        : "r"((A)[0]), "r"((A)[1]), "r"((A)[2]), "r"((A)[3]), "r"(B0), "r"(B1))

// ---------------- setup: weight split + zero counters (fused) ----------------
__global__ void k_wsetup(const float* __restrict__ W1, const float* __restrict__ W2,
                         const float* __restrict__ Wc1)
{
    int i = blockIdx.x*blockDim.x + threadIdx.x;
    if (i < RN) g_cnt[i] = 0;
    if (i >= 7*128*128) return;
    int slot = i >> 14, rem = i & 16383;
    int n = rem >> 7, k = rem & 127;
    float w;
    if (slot < 3)      w = W1[slot*16384 + k*128 + n];
    else if (slot < 6) w = W2[(slot-3)*16384 + k*128 + n];
    else               w = Wc1[k*128 + n];
    __nv_bfloat16 hi = __float2bfloat16(w);
    __nv_bfloat16 lo = __float2bfloat16(w - __bfloat162float(hi));
    g_wh[i] = hi;
    g_wl[i] = lo;
}

// ---------------- CSR build ----------------
__global__ void k_count(const int* __restrict__ edst) {
    int i = blockIdx.x*blockDim.x + threadIdx.x;
    if (i < RE) atomicAdd(&g_cnt[(i/EE)*NN + edst[i]], 1);
}
__device__ __forceinline__ int warp_incl_scan(int v) {
    int lane = threadIdx.x & 31;
    #pragma unroll
    for (int o = 1; o < 32; o <<= 1) {
        int t = __shfl_up_sync(0xffffffffu, v, o);
        if (lane >= o) v += t;
    }
    return v;
}
__global__ void k_scan_local() {
    __shared__ int ws[32];
    int i = blockIdx.x*1024 + threadIdx.x;
    int v = (i < RN) ? g_cnt[i] : 0;
    int incl = warp_incl_scan(v);
    int lane = threadIdx.x & 31, w = threadIdx.x >> 5;
    if (lane == 31) ws[w] = incl;
    __syncthreads();
    if (w == 0) { int b = ws[lane]; b = warp_incl_scan(b); ws[lane] = b; }
    __syncthreads();
    int off = (w > 0) ? ws[w-1] : 0;
    if (i < RN) g_off[i] = off + incl - v;
    if (threadIdx.x == 0) g_bsum[blockIdx.x] = ws[31];
}
__global__ void k_scan_bsum(int nb) {
    __shared__ int ws[8];
    int v = (threadIdx.x < nb) ? g_bsum[threadIdx.x] : 0;
    int incl = warp_incl_scan(v);
    int lane = threadIdx.x & 31, w = threadIdx.x >> 5;
    if (lane == 31) ws[w] = incl;
    __syncthreads();
    if (w == 0) { int b = (lane < 8) ? ws[lane] : 0; b = warp_incl_scan(b); if (lane < 8) ws[lane] = b; }
    __syncthreads();
    int off = (w > 0) ? ws[w-1] : 0;
    if (threadIdx.x < nb) g_bsum[threadIdx.x] = off + incl - v;
}
__global__ void k_scan_add() {
    int i = blockIdx.x*1024 + threadIdx.x;
    if (i < RN) {
        int o = g_off[i] + g_bsum[blockIdx.x];
        g_off[i] = o;
        g_cnt[i] = o;
    }
    if (i == 0) g_off[RN] = RE;
}
__global__ void k_fill(const int* __restrict__ edst) {
    int i = blockIdx.x*blockDim.x + threadIdx.x;
    if (i < RE) {
        int idx = (i/EE)*NN + edst[i];
        int p = atomicAdd(&g_cnt[idx], 1);
        g_csr[p] = i;
    }
}

// ---------------- HMMA split-bf16 GEMM, 128x128 tile, K chunked by 64 --------
// MODE 0: g_hp[r] rows (fp16) = X @ W[slot]; also g_el/g_er (fp32) from al/ar.
// MODE 1: out1[m] = relu(X@W + bc1) . wc2 + bc2
// block 256 (8 warps: 4 along M x 2 along N), warp tile 32x64.
#define ASTR 72
#define SM_BF  (4*128*ASTR)                 // 4 bf16 tiles
#define SM_TOT (SM_BF*2 + 256*4 + 256*4)    // tiles + params + partials

template<int MODE>
__global__ void __launch_bounds__(256, 2)
k_tgemm(const float* __restrict__ X, int slot0,
        const float* __restrict__ al, const float* __restrict__ ar,
        const float* __restrict__ bc1, const float* __restrict__ wc2,
        const float* __restrict__ bc2, float* __restrict__ out1)
{
    extern __shared__ char smem[];
    __nv_bfloat16* Ah = (__nv_bfloat16*)smem;       // [128][72]
    __nv_bfloat16* Av = Ah + 128*ASTR;
    __nv_bfloat16* Bh = Av + 128*ASTR;
    __nv_bfloat16* Bv = Bh + 128*ASTR;
    float* Ps = (float*)(Bv + 128*ASTR);            // 256 param floats
    float* Pt = Ps + 256;                           // 128x2 row partials (mode1)

    const int tid  = threadIdx.x;
    const int lane = tid & 31;
    const int w    = tid >> 5;
    const int wm   = w & 3;          // 0..3 along M
    const int wn   = w >> 2;         // 0..1 along N
    const int r    = blockIdx.y;
    const int slot = slot0 + r;
    const int n0   = blockIdx.x * 128;

    if (MODE == 0) Ps[tid] = (tid < 128) ? al[r*128 + tid] : ar[r*128 + tid - 128];
    else           Ps[tid] = (tid < 128) ? bc1[tid]        : wc2[tid - 128];

    const __nv_bfloat16* wh = g_wh + (size_t)slot*16384;
    const __nv_bfloat16* wl = g_wl + (size_t)slot*16384;

    const uint32_t sAh = smem_u32(Ah), sAv = smem_u32(Av);
    const uint32_t sBh = smem_u32(Bh), sBv = smem_u32(Bv);
    const uint32_t aOff = ((wm*32 + (lane & 15))*ASTR + (lane >> 4)*8) * 2;
    const uint32_t bOff = ((wn*64 + ((lane >> 4) & 1)*8 + (lane & 7))*ASTR
                           + ((lane >> 3) & 1)*8) * 2;

    float acc[2][8][4];
    #pragma unroll
    for (int mt = 0; mt < 2; mt++)
        #pragma unroll
        for (int nt = 0; nt < 8; nt++)
            #pragma unroll
            for (int q = 0; q < 4; q++) acc[mt][nt][q] = 0.f;

    #pragma unroll
    for (int ch = 0; ch < 2; ch++) {
        __syncthreads();
        #pragma unroll
        for (int i = 0; i < 4; i++) {
            int idx = tid + i*256;
            int n = idx >> 3, k = (idx & 7) << 3;
            *(uint4*)&Bh[n*ASTR + k] = *(const uint4*)&wh[n*128 + ch*64 + k];
            *(uint4*)&Bv[n*ASTR + k] = *(const uint4*)&wl[n*128 + ch*64 + k];
        }
        #pragma unroll
        for (int i = 0; i < 4; i++) {
            int idx = tid + i*256;
            int m = idx >> 3, k = (idx & 7) << 3;
            int gm = n0 + m;
            float v[8] = {0.f,0.f,0.f,0.f,0.f,0.f,0.f,0.f};
            if (gm < NN) {
                const float* xp = X + (size_t)gm*128 + ch*64 + k;
                float4 x0 = *(const float4*)xp;
                float4 x1 = *(const float4*)(xp + 4);
                v[0]=x0.x; v[1]=x0.y; v[2]=x0.z; v[3]=x0.w;
                v[4]=x1.x; v[5]=x1.y; v[6]=x1.z; v[7]=x1.w;
            }
            __nv_bfloat16 hh[8], ll[8];
            #pragma unroll
            for (int t = 0; t < 8; t++) {
                hh[t] = __float2bfloat16(v[t]);
                ll[t] = __float2bfloat16(v[t] - __bfloat162float(hh[t]));
            }
            *(uint4*)&Ah[m*ASTR + k] = *(const uint4*)hh;
            *(uint4*)&Av[m*ASTR + k] = *(const uint4*)ll;
        }
        __syncthreads();

        #pragma unroll
        for (int ks = 0; ks < 4; ks++) {
            uint32_t ah[2][4], av[2][4];
            #pragma unroll
            for (int mt = 0; mt < 2; mt++) {
                LDSM4(ah[mt], sAh + aOff + mt*(16*ASTR*2) + ks*32);
                LDSM4(av[mt], sAv + aOff + mt*(16*ASTR*2) + ks*32);
            }
            #pragma unroll
            for (int p = 0; p < 4; p++) {
                uint32_t bh[4], bv[4];
                LDSM4(bh, sBh + bOff + p*(16*ASTR*2) + ks*32);
                LDSM4(bv, sBv + bOff + p*(16*ASTR*2) + ks*32);
                #pragma unroll
                for (int mt = 0; mt < 2; mt++) {
                    MMA(acc[mt][2*p],   ah[mt], bh[0], bh[1]);
                    MMA(acc[mt][2*p],   ah[mt], bv[0], bv[1]);
                    MMA(acc[mt][2*p],   av[mt], bh[0], bh[1]);
                    MMA(acc[mt][2*p+1], ah[mt], bh[2], bh[3]);
                    MMA(acc[mt][2*p+1], ah[mt], bv[2], bv[3]);
                    MMA(acc[mt][2*p+1], av[mt], bh[2], bh[3]);
                }
            }
        }
    }

    // ---- epilogue ----
    const int g  = lane >> 2;
    const int c2 = (lane & 3) * 2;

    if (MODE == 0) {
        #pragma unroll
        for (int mt = 0; mt < 2; mt++) {
            #pragma unroll
            for (int rh = 0; rh < 2; rh++) {
                int gm = n0 + wm*32 + mt*16 + rh*8 + g;
                bool ok = gm < NN;
                if (ok) {
                    __half* op = g_hp + ((size_t)r*NN + gm)*128;
                    #pragma unroll
                    for (int nt = 0; nt < 8; nt++) {
                        int n = wn*64 + nt*8 + c2;
                        *(__half2*)&op[n] =
                            __floats2half2_rn(acc[mt][nt][rh*2], acc[mt][nt][rh*2+1]);
                    }
                }
                #pragma unroll
                for (int j = 0; j < 4; j++) {
                    float el = 0.f, er = 0.f;
                    #pragma unroll
                    for (int t = 0; t < 2; t++) {
                        int nt = 2*j + t;
                        int n = wn*64 + nt*8 + c2;
                        float v0 = acc[mt][nt][rh*2], v1 = acc[mt][nt][rh*2+1];
                        el += v0*Ps[n] + v1*Ps[n+1];
                        er += v0*Ps[128+n] + v1*Ps[128+n+1];
                    }
                    el += __shfl_xor_sync(0xffffffffu, el, 1);
                    er += __shfl_xor_sync(0xffffffffu, er, 1);
                    el += __shfl_xor_sync(0xffffffffu, el, 2);
                    er += __shfl_xor_sync(0xffffffffu, er, 2);
                    if ((lane & 3) == 0 && ok) {
                        g_el[((size_t)r*NN + gm)*HH + wn*4 + j] = el;
                        g_er[((size_t)r*NN + gm)*HH + wn*4 + j] = er;
                    }
                }
            }
        }
    } else {
        #pragma unroll
        for (int mt = 0; mt < 2; mt++) {
            #pragma unroll
            for (int rh = 0; rh < 2; rh++) {
                float s = 0.f;
                #pragma unroll
                for (int nt = 0; nt < 8; nt++) {
                    int n = wn*64 + nt*8 + c2;
                    s += fmaxf(acc[mt][nt][rh*2]   + Ps[n],   0.f) * Ps[128+n];
                    s += fmaxf(acc[mt][nt][rh*2+1] + Ps[n+1], 0.f) * Ps[128+n+1];
                }
                s += __shfl_xor_sync(0xffffffffu, s, 1);
                s += __shfl_xor_sync(0xffffffffu, s, 2);
                if ((lane & 3) == 0)
                    Pt[(wm*32 + mt*16 + rh*8 + g)*2 + wn] = s;
            }
        }
        __syncthreads();
        if (tid < 128) {
            int gm = n0 + tid;
            if (gm < NN) out1[gm] = Pt[tid*2] + Pt[tid*2+1] + bc2[0];
        }
    }
}

// ---------------- warp-per-node single-pass softmax-aggregate (fp16 gather) --
__global__ void k_agg(const int* __restrict__ esrc, const float* __restrict__ bias,
                      const float* __restrict__ lng, const float* __restrict__ lnb,
                      float* __restrict__ out, int mode)
{
    int warp = (blockIdx.x*blockDim.x + threadIdx.x) >> 5;
    if (warp >= NN) return;
    int v = warp;
    int lane = threadIdx.x & 31;
    int h = lane >> 2;

    float ax = 0.f, ay = 0.f, az = 0.f, aw = 0.f;

    #pragma unroll
    for (int r = 0; r < RR; r++) {
        int base = r*NN + v;
        int st = g_off[base], d = g_off[base+1] - st;
        if (d == 0) continue;
        float erv = __ldg(&g_er[(size_t)base*HH + h]);

        float nx = 0.f, ny = 0.f, nz = 0.f, nw = 0.f, den = 0.f;
        int s_next = __ldg(&esrc[__ldg(&g_csr[st])]);
        for (int i = 0; i < d; i++) {
            int s = s_next;
            if (i + 1 < d) s_next = __ldg(&esrc[__ldg(&g_csr[st + i + 1])]);
            float x = __ldg(&g_el[(size_t)(r*NN + s)*HH + h]) + erv;
            x = x > 0.f ? x : NEG_SLOPE*x;
            float e = __expf(x);
            den += e;
            uint2 u = *(const uint2*)&g_hp[((size_t)r*NN + s)*DD + lane*4];
            float2 f0 = __half22float2(*(__half2*)&u.x);
            float2 f1 = __half22float2(*(__half2*)&u.y);
            nx += e*f0.x; ny += e*f0.y; nz += e*f1.x; nw += e*f1.y;
        }
        float rd = 1.0f / den;
        ax += nx*rd; ay += ny*rd; az += nz*rd; aw += nw*rd;
    }

    int c = lane*4;
    ax += bias[c+0] + bias[128+c+0] + bias[256+c+0];
    ay += bias[c+1] + bias[128+c+1] + bias[256+c+1];
    az += bias[c+2] + bias[128+c+2] + bias[256+c+2];
    aw += bias[c+3] + bias[128+c+3] + bias[256+c+3];

    if (mode == 0) {
        float4 o = make_float4(fmaxf(ax,0.f), fmaxf(ay,0.f), fmaxf(az,0.f), fmaxf(aw,0.f));
        *(float4*)&out[(size_t)v*DD + c] = o;
    } else {
        float4 hr = *(const float4*)&g_h1[(size_t)v*DD + c];
        ax += hr.x; ay += hr.y; az += hr.z; aw += hr.w;
        float s  = ax + ay + az + aw;
        float ss = ax*ax + ay*ay + az*az + aw*aw;
        #pragma unroll
        for (int o = 16; o; o >>= 1) {
            s  += __shfl_xor_sync(0xffffffffu, s,  o);
            ss += __shfl_xor_sync(0xffffffffu, ss, o);
        }
        float mu  = s * (1.0f/128.0f);
        float var = ss * (1.0f/128.0f) - mu*mu;
        float inv = rsqrtf(var + LN_EPS);
        float4 o;
        o.x = (ax - mu)*inv*lng[c+0] + lnb[c+0];
        o.y = (ay - mu)*inv*lng[c+1] + lnb[c+1];
        o.z = (az - mu)*inv*lng[c+2] + lnb[c+2];
        o.w = (aw - mu)*inv*lng[c+3] + lnb[c+3];
        *(float4*)&out[(size_t)v*DD + c] = o;
    }
}

// ---------------- launch ----------------
extern "C" void kernel_launch(void* const* d_in, const int* in_sizes, int n_in,
                              void* d_out, int out_size)
{
    const float* feat = (const float*)d_in[0];
    const int*   esrc = (const int*)d_in[1];
    const int*   edst = (const int*)d_in[2];
    const float* W1   = (const float*)d_in[3];
    const float* al1  = (const float*)d_in[4];
    const float* ar1  = (const float*)d_in[5];
    const float* b1   = (const float*)d_in[6];
    const float* W2   = (const float*)d_in[7];
    const float* al2  = (const float*)d_in[8];
    const float* ar2  = (const float*)d_in[9];
    const float* b2   = (const float*)d_in[10];
    const float* lng  = (const float*)d_in[11];
    const float* lnb  = (const float*)d_in[12];
    const float* Wc1  = (const float*)d_in[13];
    const float* bc1  = (const float*)d_in[14];
    const float* Wc2  = (const float*)d_in[15];
    const float* bc2  = (const float*)d_in[16];
    float* out = (float*)d_out;

    float *h1, *hn;
    cudaGetSymbolAddress((void**)&h1, g_h1);
    cudaGetSymbolAddress((void**)&hn, g_hn);

    cudaFuncSetAttribute(k_tgemm<0>, cudaFuncAttributeMaxDynamicSharedMemorySize, SM_TOT);
    cudaFuncSetAttribute(k_tgemm<1>, cudaFuncAttributeMaxDynamicSharedMemorySize, SM_TOT);

    const int NB = (RN + 1023) / 1024;
    dim3 gp((NN + 127)/128, RR);
    dim3 g1((NN + 127)/128, 1);
    int aggBlocks = (NN*32 + 255)/256;

    // launch #4 is the layer-1 GEMM (for ncu capture)
    k_wsetup<<<(RN + 255)/256, 256>>>(W1, W2, Wc1);                        // 1 (also zeroes cnt)
    k_count<<<(RE+255)/256, 256>>>(edst);                                  // 2
    k_scan_local<<<NB, 1024>>>();                                          // 3
    k_tgemm<0><<<gp, 256, SM_TOT>>>(feat, 0, al1, ar1, 0, 0, 0, 0);        // 4  <-- profiled
    k_scan_bsum<<<1, 256>>>(NB);                                           // 5
    k_scan_add<<<NB, 1024>>>();                                            // 6
    k_fill<<<(RE+255)/256, 256>>>(edst);                                   // 7

    k_agg<<<aggBlocks, 256>>>(esrc, b1, nullptr, nullptr, h1, 0);          // 8
    k_tgemm<0><<<gp, 256, SM_TOT>>>(h1, 3, al2, ar2, 0, 0, 0, 0);          // 9
    k_agg<<<aggBlocks, 256>>>(esrc, b2, lng, lnb, hn, 1);                  // 10
    k_tgemm<1><<<g1, 256, SM_TOT>>>(hn, 6, 0, 0, bc1, Wc2, bc2, out);      // 11
}

// round 7
// speedup vs baseline: 2.5737x; 1.0227x over previous
#include <cuda_runtime.h>
#include <cuda_bf16.h>
#include <cuda_fp16.h>
#include <cstdint>

#define NN 50000
#define EE 400000
#define RR 3
#define DD 128
#define HH 8
#define RN (RR*NN)
#define RE (RR*EE)
#define NEG_SLOPE 0.2f
#define LN_EPS 1e-5f

// ---------------- scratch (device globals; no allocs allowed) ----------------
__device__ __align__(128) __half g_hp[(size_t)RR*NN*DD];
__device__ __align__(128) float g_el[(size_t)RN*HH];
__device__ __align__(128) float g_er[(size_t)RN*HH];
__device__ __align__(128) float g_h1[(size_t)NN*DD];
__device__ __align__(128) float g_hn[(size_t)NN*DD];
__device__ __align__(128) int   g_off[RN+1];
__device__ __align__(128) int   g_cnt[RN];
__device__ __align__(128) int   g_csr[RE];
__device__ __align__(128) int   g_bsum[256];
// pre-split transposed weights, 7 slots: W1 r0-2, W2 r0-2, Wc1. layout [slot][n][k]
__device__ __align__(128) __nv_bfloat16 g_wh[7*128*128];
__device__ __align__(128) __nv_bfloat16 g_wl[7*128*128];

__device__ __forceinline__ uint32_t smem_u32(const void* p) {
    uint32_t a;
    asm("{ .reg .u64 t; cvta.to.shared.u64 t, %1; cvt.u32.u64 %0, t; }" : "=r"(a) : "l"(p));
    return a;
}

#define LDSM4(R, A) \
    asm volatile("ldmatrix.sync.aligned.m8n8.x4.shared.b16 {%0,%1,%2,%3}, [%4];" \
        : "=r"((R)[0]), "=r"((R)[1]), "=r"((R)[2]), "=r"((R)[3]) : "r"(A))

#define MMA(C, A, B0, B1) \
    asm volatile("mma.sync.aligned.m16n8k16.row.col.f32.bf16.bf16.f32 " \
        "{%0,%1,%2,%3}, {%4,%5,%6,%7}, {%8,%9}, {%0,%1,%2,%3};" \
        : "+f"((C)[0]), "+f"((C)[1]), "+f"((C)[2]), "+f"((C)[3]) \
        : "r"((A)[0]), "r"((A)[1]), "r"((A)[2]), "r"((A)[3]), "r"(B0), "r"(B1))

// ---------------- setup: weight split + zero counters (fused) ----------------
__global__ void k_wsetup(const float* __restrict__ W1, const float* __restrict__ W2,
                         const float* __restrict__ Wc1)
{
    int i = blockIdx.x*blockDim.x + threadIdx.x;
    if (i < RN) g_cnt[i] = 0;
    if (i >= 7*128*128) return;
    int slot = i >> 14, rem = i & 16383;
    int n = rem >> 7, k = rem & 127;
    float w;
    if (slot < 3)      w = W1[slot*16384 + k*128 + n];
    else if (slot < 6) w = W2[(slot-3)*16384 + k*128 + n];
    else               w = Wc1[k*128 + n];
    __nv_bfloat16 hi = __float2bfloat16(w);
    __nv_bfloat16 lo = __float2bfloat16(w - __bfloat162float(hi));
    g_wh[i] = hi;
    g_wl[i] = lo;
}

// ---------------- CSR build ----------------
__global__ void k_count(const int* __restrict__ edst) {
    int i = blockIdx.x*blockDim.x + threadIdx.x;
    if (i < RE) atomicAdd(&g_cnt[(i/EE)*NN + edst[i]], 1);
}
__device__ __forceinline__ int warp_incl_scan(int v) {
    int lane = threadIdx.x & 31;
    #pragma unroll
    for (int o = 1; o < 32; o <<= 1) {
        int t = __shfl_up_sync(0xffffffffu, v, o);
        if (lane >= o) v += t;
    }
    return v;
}
__global__ void k_scan_local() {
    __shared__ int ws[32];
    int i = blockIdx.x*1024 + threadIdx.x;
    int v = (i < RN) ? g_cnt[i] : 0;
    int incl = warp_incl_scan(v);
    int lane = threadIdx.x & 31, w = threadIdx.x >> 5;
    if (lane == 31) ws[w] = incl;
    __syncthreads();
    if (w == 0) { int b = ws[lane]; b = warp_incl_scan(b); ws[lane] = b; }
    __syncthreads();
    int off = (w > 0) ? ws[w-1] : 0;
    if (i < RN) g_off[i] = off + incl - v;
    if (threadIdx.x == 0) g_bsum[blockIdx.x] = ws[31];
}
__global__ void k_scan_bsum(int nb) {
    __shared__ int ws[8];
    int v = (threadIdx.x < nb) ? g_bsum[threadIdx.x] : 0;
    int incl = warp_incl_scan(v);
    int lane = threadIdx.x & 31, w = threadIdx.x >> 5;
    if (lane == 31) ws[w] = incl;
    __syncthreads();
    if (w == 0) { int b = (lane < 8) ? ws[lane] : 0; b = warp_incl_scan(b); if (lane < 8) ws[lane] = b; }
    __syncthreads();
    int off = (w > 0) ? ws[w-1] : 0;
    if (threadIdx.x < nb) g_bsum[threadIdx.x] = off + incl - v;
}
__global__ void k_scan_add() {
    int i = blockIdx.x*1024 + threadIdx.x;
    if (i < RN) {
        int o = g_off[i] + g_bsum[blockIdx.x];
        g_off[i] = o;
        g_cnt[i] = o;
    }
    if (i == 0) g_off[RN] = RE;
}
__global__ void k_fill(const int* __restrict__ edst) {
    int i = blockIdx.x*blockDim.x + threadIdx.x;
    if (i < RE) {
        int idx = (i/EE)*NN + edst[i];
        int p = atomicAdd(&g_cnt[idx], 1);
        g_csr[p] = i;
    }
}

// ---------------- projection GEMM: convert A once, loop 3 relations ---------
// g_hp[r] rows (fp16) = X @ W[slot0+r]; g_el/g_er (fp32) from al/ar.
// block 256 (8 warps: 4 M x 2 N), warp tile 32x64. A full-K in smem.
#define ASTRA 136
#define ASTRB 72
#define SM_PROJ ((2*128*ASTRA + 2*128*ASTRB)*2 + 1024)

__global__ void __launch_bounds__(256, 2)
k_proj(const float* __restrict__ X, int slot0,
       const float* __restrict__ al, const float* __restrict__ ar)
{
    extern __shared__ char smem[];
    __nv_bfloat16* Ah = (__nv_bfloat16*)smem;        // [128][136]
    __nv_bfloat16* Av = Ah + 128*ASTRA;
    __nv_bfloat16* Bh = Av + 128*ASTRA;              // [128][72]
    __nv_bfloat16* Bv = Bh + 128*ASTRB;
    float* Ps = (float*)(Bv + 128*ASTRB);            // 256 params (al|ar)

    const int tid  = threadIdx.x;
    const int lane = tid & 31;
    const int w    = tid >> 5;
    const int wm   = w & 3;
    const int wn   = w >> 2;
    const int n0   = blockIdx.x * 128;

    // ---- stage A (full K), split fp32 -> bf16 hi/lo ----
    #pragma unroll
    for (int i = 0; i < 8; i++) {
        int idx = tid + i*256;
        int m = idx >> 4, k = (idx & 15) << 3;
        int gm = n0 + m;
        float v[8] = {0.f,0.f,0.f,0.f,0.f,0.f,0.f,0.f};
        if (gm < NN) {
            const float* xp = X + (size_t)gm*128 + k;
            float4 x0 = *(const float4*)xp;
            float4 x1 = *(const float4*)(xp + 4);
            v[0]=x0.x; v[1]=x0.y; v[2]=x0.z; v[3]=x0.w;
            v[4]=x1.x; v[5]=x1.y; v[6]=x1.z; v[7]=x1.w;
        }
        __nv_bfloat16 hh[8], ll[8];
        #pragma unroll
        for (int t = 0; t < 8; t++) {
            hh[t] = __float2bfloat16(v[t]);
            ll[t] = __float2bfloat16(v[t] - __bfloat162float(hh[t]));
        }
        *(uint4*)&Ah[m*ASTRA + k] = *(const uint4*)hh;
        *(uint4*)&Av[m*ASTRA + k] = *(const uint4*)ll;
    }

    const uint32_t sAh = smem_u32(Ah), sAv = smem_u32(Av);
    const uint32_t sBh = smem_u32(Bh), sBv = smem_u32(Bv);
    const uint32_t aOff = ((wm*32 + (lane & 15))*ASTRA + (lane >> 4)*8) * 2;
    const uint32_t bOff = ((wn*64 + ((lane >> 4) & 1)*8 + (lane & 7))*ASTRB
                           + ((lane >> 3) & 1)*8) * 2;
    const int g  = lane >> 2;
    const int c2 = (lane & 3) * 2;

    for (int r = 0; r < RR; r++) {
        const int slot = slot0 + r;
        const __nv_bfloat16* wh = g_wh + (size_t)slot*16384;
        const __nv_bfloat16* wl = g_wl + (size_t)slot*16384;

        float acc[2][8][4];
        #pragma unroll
        for (int mt = 0; mt < 2; mt++)
            #pragma unroll
            for (int nt = 0; nt < 8; nt++)
                #pragma unroll
                for (int q = 0; q < 4; q++) acc[mt][nt][q] = 0.f;

        #pragma unroll
        for (int ch = 0; ch < 2; ch++) {
            __syncthreads();   // A staged / prev B consumed / prev epilogue Ps reads done
            if (ch == 0)
                Ps[tid] = (tid < 128) ? al[r*128 + tid] : ar[r*128 + tid - 128];
            #pragma unroll
            for (int i = 0; i < 4; i++) {
                int idx = tid + i*256;
                int n = idx >> 3, k = (idx & 7) << 3;
                *(uint4*)&Bh[n*ASTRB + k] = *(const uint4*)&wh[n*128 + ch*64 + k];
                *(uint4*)&Bv[n*ASTRB + k] = *(const uint4*)&wl[n*128 + ch*64 + k];
            }
            __syncthreads();

            #pragma unroll
            for (int ks = 0; ks < 4; ks++) {
                const uint32_t ka = ch*128 + ks*32;   // bytes into A k-dim
                uint32_t ah[2][4], av[2][4];
                #pragma unroll
                for (int mt = 0; mt < 2; mt++) {
                    LDSM4(ah[mt], sAh + aOff + mt*(16*ASTRA*2) + ka);
                    LDSM4(av[mt], sAv + aOff + mt*(16*ASTRA*2) + ka);
                }
                #pragma unroll
                for (int p = 0; p < 4; p++) {
                    uint32_t bh[4], bv[4];
                    LDSM4(bh, sBh + bOff + p*(16*ASTRB*2) + ks*32);
                    LDSM4(bv, sBv + bOff + p*(16*ASTRB*2) + ks*32);
                    #pragma unroll
                    for (int mt = 0; mt < 2; mt++) {
                        MMA(acc[mt][2*p],   ah[mt], bh[0], bh[1]);
                        MMA(acc[mt][2*p],   ah[mt], bv[0], bv[1]);
                        MMA(acc[mt][2*p],   av[mt], bh[0], bh[1]);
                        MMA(acc[mt][2*p+1], ah[mt], bh[2], bh[3]);
                        MMA(acc[mt][2*p+1], ah[mt], bv[2], bv[3]);
                        MMA(acc[mt][2*p+1], av[mt], bh[2], bh[3]);
                    }
                }
            }
        }

        // ---- epilogue for relation r ----
        #pragma unroll
        for (int mt = 0; mt < 2; mt++) {
            #pragma unroll
            for (int rh = 0; rh < 2; rh++) {
                int gm = n0 + wm*32 + mt*16 + rh*8 + g;
                bool ok = gm < NN;
                if (ok) {
                    __half* op = g_hp + ((size_t)r*NN + gm)*128;
                    #pragma unroll
                    for (int nt = 0; nt < 8; nt++) {
                        int n = wn*64 + nt*8 + c2;
                        *(__half2*)&op[n] =
                            __floats2half2_rn(acc[mt][nt][rh*2], acc[mt][nt][rh*2+1]);
                    }
                }
                #pragma unroll
                for (int j = 0; j < 4; j++) {
                    float el = 0.f, er = 0.f;
                    #pragma unroll
                    for (int t = 0; t < 2; t++) {
                        int nt = 2*j + t;
                        int n = wn*64 + nt*8 + c2;
                        float v0 = acc[mt][nt][rh*2], v1 = acc[mt][nt][rh*2+1];
                        el += v0*Ps[n] + v1*Ps[n+1];
                        er += v0*Ps[128+n] + v1*Ps[128+n+1];
                    }
                    el += __shfl_xor_sync(0xffffffffu, el, 1);
                    er += __shfl_xor_sync(0xffffffffu, er, 1);
                    el += __shfl_xor_sync(0xffffffffu, el, 2);
                    er += __shfl_xor_sync(0xffffffffu, er, 2);
                    if ((lane & 3) == 0 && ok) {
                        g_el[((size_t)r*NN + gm)*HH + wn*4 + j] = el;
                        g_er[((size_t)r*NN + gm)*HH + wn*4 + j] = er;
                    }
                }
            }
        }
    }
}

// ---------------- classifier GEMM (old chunked path, single weight) ----------
#define SM_CLS (4*128*ASTRB*2 + 256*4 + 256*4)

__global__ void __launch_bounds__(256, 2)
k_cls(const float* __restrict__ X,
      const float* __restrict__ bc1, const float* __restrict__ wc2,
      const float* __restrict__ bc2, float* __restrict__ out1)
{
    extern __shared__ char smem[];
    __nv_bfloat16* Ah = (__nv_bfloat16*)smem;
    __nv_bfloat16* Av = Ah + 128*ASTRB;
    __nv_bfloat16* Bh = Av + 128*ASTRB;
    __nv_bfloat16* Bv = Bh + 128*ASTRB;
    float* Ps = (float*)(Bv + 128*ASTRB);
    float* Pt = Ps + 256;

    const int tid  = threadIdx.x;
    const int lane = tid & 31;
    const int w    = tid >> 5;
    const int wm   = w & 3;
    const int wn   = w >> 2;
    const int n0   = blockIdx.x * 128;

    Ps[tid] = (tid < 128) ? bc1[tid] : wc2[tid - 128];

    const __nv_bfloat16* wh = g_wh + (size_t)6*16384;
    const __nv_bfloat16* wl = g_wl + (size_t)6*16384;

    const uint32_t sAh = smem_u32(Ah), sAv = smem_u32(Av);
    const uint32_t sBh = smem_u32(Bh), sBv = smem_u32(Bv);
    const uint32_t aOff = ((wm*32 + (lane & 15))*ASTRB + (lane >> 4)*8) * 2;
    const uint32_t bOff = ((wn*64 + ((lane >> 4) & 1)*8 + (lane & 7))*ASTRB
                           + ((lane >> 3) & 1)*8) * 2;

    float acc[2][8][4];
    #pragma unroll
    for (int mt = 0; mt < 2; mt++)
        #pragma unroll
        for (int nt = 0; nt < 8; nt++)
            #pragma unroll
            for (int q = 0; q < 4; q++) acc[mt][nt][q] = 0.f;

    #pragma unroll
    for (int ch = 0; ch < 2; ch++) {
        __syncthreads();
        #pragma unroll
        for (int i = 0; i < 4; i++) {
            int idx = tid + i*256;
            int n = idx >> 3, k = (idx & 7) << 3;
            *(uint4*)&Bh[n*ASTRB + k] = *(const uint4*)&wh[n*128 + ch*64 + k];
            *(uint4*)&Bv[n*ASTRB + k] = *(const uint4*)&wl[n*128 + ch*64 + k];
        }
        #pragma unroll
        for (int i = 0; i < 4; i++) {
            int idx = tid + i*256;
            int m = idx >> 3, k = (idx & 7) << 3;
            int gm = n0 + m;
            float v[8] = {0.f,0.f,0.f,0.f,0.f,0.f,0.f,0.f};
            if (gm < NN) {
                const float* xp = X + (size_t)gm*128 + ch*64 + k;
                float4 x0 = *(const float4*)xp;
                float4 x1 = *(const float4*)(xp + 4);
                v[0]=x0.x; v[1]=x0.y; v[2]=x0.z; v[3]=x0.w;
                v[4]=x1.x; v[5]=x1.y; v[6]=x1.z; v[7]=x1.w;
            }
            __nv_bfloat16 hh[8], ll[8];
            #pragma unroll
            for (int t = 0; t < 8; t++) {
                hh[t] = __float2bfloat16(v[t]);
                ll[t] = __float2bfloat16(v[t] - __bfloat162float(hh[t]));
            }
            *(uint4*)&Ah[m*ASTRB + k] = *(const uint4*)hh;
            *(uint4*)&Av[m*ASTRB + k] = *(const uint4*)ll;
        }
        __syncthreads();

        #pragma unroll
        for (int ks = 0; ks < 4; ks++) {
            uint32_t ah[2][4], av[2][4];
            #pragma unroll
            for (int mt = 0; mt < 2; mt++) {
                LDSM4(ah[mt], sAh + aOff + mt*(16*ASTRB*2) + ks*32);
                LDSM4(av[mt], sAv + aOff + mt*(16*ASTRB*2) + ks*32);
            }
            #pragma unroll
            for (int p = 0; p < 4; p++) {
                uint32_t bh[4], bv[4];
                LDSM4(bh, sBh + bOff + p*(16*ASTRB*2) + ks*32);
                LDSM4(bv, sBv + bOff + p*(16*ASTRB*2) + ks*32);
                #pragma unroll
                for (int mt = 0; mt < 2; mt++) {
                    MMA(acc[mt][2*p],   ah[mt], bh[0], bh[1]);
                    MMA(acc[mt][2*p],   ah[mt], bv[0], bv[1]);
                    MMA(acc[mt][2*p],   av[mt], bh[0], bh[1]);
                    MMA(acc[mt][2*p+1], ah[mt], bh[2], bh[3]);
                    MMA(acc[mt][2*p+1], ah[mt], bv[2], bv[3]);
                    MMA(acc[mt][2*p+1], av[mt], bh[2], bh[3]);
                }
            }
        }
    }

    const int g  = lane >> 2;
    const int c2 = (lane & 3) * 2;
    #pragma unroll
    for (int mt = 0; mt < 2; mt++) {
        #pragma unroll
        for (int rh = 0; rh < 2; rh++) {
            float s = 0.f;
            #pragma unroll
            for (int nt = 0; nt < 8; nt++) {
                int n = wn*64 + nt*8 + c2;
                s += fmaxf(acc[mt][nt][rh*2]   + Ps[n],   0.f) * Ps[128+n];
                s += fmaxf(acc[mt][nt][rh*2+1] + Ps[n+1], 0.f) * Ps[128+n+1];
            }
            s += __shfl_xor_sync(0xffffffffu, s, 1);
            s += __shfl_xor_sync(0xffffffffu, s, 2);
            if ((lane & 3) == 0)
                Pt[(wm*32 + mt*16 + rh*8 + g)*2 + wn] = s;
        }
    }
    __syncthreads();
    if (tid < 128) {
        int gm = n0 + tid;
        if (gm < NN) out1[gm] = Pt[tid*2] + Pt[tid*2+1] + bc2[0];
    }
}

// ---------------- warp-per-node softmax-aggregate, unroll-4 MLP --------------
__global__ void k_agg(const int* __restrict__ esrc, const float* __restrict__ bias,
                      const float* __restrict__ lng, const float* __restrict__ lnb,
                      float* __restrict__ out, int mode)
{
    int warp = (blockIdx.x*blockDim.x + threadIdx.x) >> 5;
    if (warp >= NN) return;
    int v = warp;
    int lane = threadIdx.x & 31;
    int h = lane >> 2;

    float ax = 0.f, ay = 0.f, az = 0.f, aw = 0.f;

    #pragma unroll
    for (int r = 0; r < RR; r++) {
        int base = r*NN + v;
        int st = g_off[base], d = g_off[base+1] - st;
        if (d == 0) continue;
        float erv = __ldg(&g_er[(size_t)base*HH + h]);
        const __half* hpr = g_hp + (size_t)r*NN*DD;
        const float*  elr = g_el + (size_t)r*NN*HH;

        float nx = 0.f, ny = 0.f, nz = 0.f, nw = 0.f, den = 0.f;
        int i = 0;
        for (; i + 4 <= d; i += 4) {
            int e0 = __ldg(&g_csr[st+i]),   e1 = __ldg(&g_csr[st+i+1]);
            int e2 = __ldg(&g_csr[st+i+2]), e3 = __ldg(&g_csr[st+i+3]);
            int s0 = __ldg(&esrc[e0]), s1 = __ldg(&esrc[e1]);
            int s2 = __ldg(&esrc[e2]), s3 = __ldg(&esrc[e3]);
            float x0 = __ldg(&elr[(size_t)s0*HH + h]) + erv;
            float x1 = __ldg(&elr[(size_t)s1*HH + h]) + erv;
            float x2 = __ldg(&elr[(size_t)s2*HH + h]) + erv;
            float x3 = __ldg(&elr[(size_t)s3*HH + h]) + erv;
            uint2 u0 = *(const uint2*)&hpr[(size_t)s0*DD + lane*4];
            uint2 u1 = *(const uint2*)&hpr[(size_t)s1*DD + lane*4];
            uint2 u2 = *(const uint2*)&hpr[(size_t)s2*DD + lane*4];
            uint2 u3 = *(const uint2*)&hpr[(size_t)s3*DD + lane*4];
            x0 = x0 > 0.f ? x0 : NEG_SLOPE*x0;
            x1 = x1 > 0.f ? x1 : NEG_SLOPE*x1;
            x2 = x2 > 0.f ? x2 : NEG_SLOPE*x2;
            x3 = x3 > 0.f ? x3 : NEG_SLOPE*x3;
            float q0 = __expf(x0), q1 = __expf(x1), q2 = __expf(x2), q3 = __expf(x3);
            den += (q0 + q1) + (q2 + q3);
            float2 a0 = __half22float2(*(__half2*)&u0.x), b0 = __half22float2(*(__half2*)&u0.y);
            float2 a1 = __half22float2(*(__half2*)&u1.x), b1 = __half22float2(*(__half2*)&u1.y);
            float2 a2 = __half22float2(*(__half2*)&u2.x), b2 = __half22float2(*(__half2*)&u2.y);
            float2 a3 = __half22float2(*(__half2*)&u3.x), b3 = __half22float2(*(__half2*)&u3.y);
            nx += q0*a0.x + q1*a1.x + q2*a2.x + q3*a3.x;
            ny += q0*a0.y + q1*a1.y + q2*a2.y + q3*a3.y;
            nz += q0*b0.x + q1*b1.x + q2*b2.x + q3*b3.x;
            nw += q0*b0.y + q1*b1.y + q2*b2.y + q3*b3.y;
        }
        for (; i < d; i++) {
            int e0 = __ldg(&g_csr[st+i]);
            int s0 = __ldg(&esrc[e0]);
            float x0 = __ldg(&elr[(size_t)s0*HH + h]) + erv;
            x0 = x0 > 0.f ? x0 : NEG_SLOPE*x0;
            float q0 = __expf(x0);
            den += q0;
            uint2 u0 = *(const uint2*)&hpr[(size_t)s0*DD + lane*4];
            float2 a0 = __half22float2(*(__half2*)&u0.x), b0 = __half22float2(*(__half2*)&u0.y);
            nx += q0*a0.x; ny += q0*a0.y; nz += q0*b0.x; nw += q0*b0.y;
        }
        float rd = 1.0f / den;
        ax += nx*rd; ay += ny*rd; az += nz*rd; aw += nw*rd;
    }

    int c = lane*4;
    ax += bias[c+0] + bias[128+c+0] + bias[256+c+0];
    ay += bias[c+1] + bias[128+c+1] + bias[256+c+1];
    az += bias[c+2] + bias[128+c+2] + bias[256+c+2];
    aw += bias[c+3] + bias[128+c+3] + bias[256+c+3];

    if (mode == 0) {
        float4 o = make_float4(fmaxf(ax,0.f), fmaxf(ay,0.f), fmaxf(az,0.f), fmaxf(aw,0.f));
        *(float4*)&out[(size_t)v*DD + c] = o;
    } else {
        float4 hr = *(const float4*)&g_h1[(size_t)v*DD + c];
        ax += hr.x; ay += hr.y; az += hr.z; aw += hr.w;
        float s  = ax + ay + az + aw;
        float ss = ax*ax + ay*ay + az*az + aw*aw;
        #pragma unroll
        for (int o = 16; o; o >>= 1) {
            s  += __shfl_xor_sync(0xffffffffu, s,  o);
            ss += __shfl_xor_sync(0xffffffffu, ss, o);
        }
        float mu  = s * (1.0f/128.0f);
        float var = ss * (1.0f/128.0f) - mu*mu;
        float inv = rsqrtf(var + LN_EPS);
        float4 o;
        o.x = (ax - mu)*inv*lng[c+0] + lnb[c+0];
        o.y = (ay - mu)*inv*lng[c+1] + lnb[c+1];
        o.z = (az - mu)*inv*lng[c+2] + lnb[c+2];
        o.w = (aw - mu)*inv*lng[c+3] + lnb[c+3];
        *(float4*)&out[(size_t)v*DD + c] = o;
    }
}

// ---------------- launch ----------------
extern "C" void kernel_launch(void* const* d_in, const int* in_sizes, int n_in,
                              void* d_out, int out_size)
{
    const float* feat = (const float*)d_in[0];
    const int*   esrc = (const int*)d_in[1];
    const int*   edst = (const int*)d_in[2];
    const float* W1   = (const float*)d_in[3];
    const float* al1  = (const float*)d_in[4];
    const float* ar1  = (const float*)d_in[5];
    const float* b1   = (const float*)d_in[6];
    const float* W2   = (const float*)d_in[7];
    const float* al2  = (const float*)d_in[8];
    const float* ar2  = (const float*)d_in[9];
    const float* b2   = (const float*)d_in[10];
    const float* lng  = (const float*)d_in[11];
    const float* lnb  = (const float*)d_in[12];
    const float* Wc1  = (const float*)d_in[13];
    const float* bc1  = (const float*)d_in[14];
    const float* Wc2  = (const float*)d_in[15];
    const float* bc2  = (const float*)d_in[16];
    float* out = (float*)d_out;

    float *h1, *hn;
    cudaGetSymbolAddress((void**)&h1, g_h1);
    cudaGetSymbolAddress((void**)&hn, g_hn);

    cudaFuncSetAttribute(k_proj, cudaFuncAttributeMaxDynamicSharedMemorySize, SM_PROJ);
    cudaFuncSetAttribute(k_cls,  cudaFuncAttributeMaxDynamicSharedMemorySize, SM_CLS);

    const int NB = (RN + 1023) / 1024;
    int gx = (NN + 127)/128;
    int aggBlocks = (NN*32 + 255)/256;

    // launch #4 is the layer-1 projection (for ncu capture)
    k_wsetup<<<(RN + 255)/256, 256>>>(W1, W2, Wc1);                        // 1 (also zeroes cnt)
    k_count<<<(RE+255)/256, 256>>>(edst);                                  // 2
    k_scan_local<<<NB, 1024>>>();                                          // 3
    k_proj<<<gx, 256, SM_PROJ>>>(feat, 0, al1, ar1);                       // 4  <-- profiled
    k_scan_bsum<<<1, 256>>>(NB);                                           // 5
    k_scan_add<<<NB, 1024>>>();                                            // 6
    k_fill<<<(RE+255)/256, 256>>>(edst);                                   // 7

    k_agg<<<aggBlocks, 256>>>(esrc, b1, nullptr, nullptr, h1, 0);          // 8
    k_proj<<<gx, 256, SM_PROJ>>>(h1, 3, al2, ar2);                         // 9
    k_agg<<<aggBlocks, 256>>>(esrc, b2, lng, lnb, hn, 1);                  // 10
    k_cls<<<gx, 256, SM_CLS>>>(hn, bc1, Wc2, bc2, out);                    // 11
}

// round 8
// speedup vs baseline: 2.8144x; 1.0935x over previous
#include <cuda_runtime.h>
#include <cuda_bf16.h>
#include <cuda_fp16.h>
#include <cstdint>

#define NN 50000
#define EE 400000
#define RR 3
#define DD 128
#define HH 8
#define RN (RR*NN)
#define RE (RR*EE)
#define NEG_SLOPE 0.2f
#define LN_EPS 1e-5f

// ---------------- scratch (device globals; no allocs allowed) ----------------
__device__ __align__(128) __half g_hp[(size_t)RR*NN*DD];
__device__ __align__(128) float g_el[(size_t)RN*HH];
__device__ __align__(128) float g_er[(size_t)RN*HH];
__device__ __align__(128) float g_h1[(size_t)NN*DD];
__device__ __align__(128) __nv_bfloat16 g_xh[(size_t)NN*DD];  // GEMM input hi split
__device__ __align__(128) __nv_bfloat16 g_xl[(size_t)NN*DD];  // GEMM input lo split
__device__ __align__(128) int   g_off[RN+1];
__device__ __align__(128) int   g_cnt[RN];
__device__ __align__(128) int   g_csr[RE];      // stores SRC NODE ids (not edge ids)
__device__ __align__(128) int   g_bsum[256];
// pre-split transposed weights, 7 slots: W1 r0-2, W2 r0-2, Wc1. layout [slot][n][k]
__device__ __align__(128) __nv_bfloat16 g_wh[7*128*128];
__device__ __align__(128) __nv_bfloat16 g_wl[7*128*128];

__device__ __forceinline__ uint32_t smem_u32(const void* p) {
    uint32_t a;
    asm("{ .reg .u64 t; cvta.to.shared.u64 t, %1; cvt.u32.u64 %0, t; }" : "=r"(a) : "l"(p));
    return a;
}

#define LDSM4(R, A) \
    asm volatile("ldmatrix.sync.aligned.m8n8.x4.shared.b16 {%0,%1,%2,%3}, [%4];" \
        : "=r"((R)[0]), "=r"((R)[1]), "=r"((R)[2]), "=r"((R)[3]) : "r"(A))

#define MMA(C, A, B0, B1) \
    asm volatile("mma.sync.aligned.m16n8k16.row.col.f32.bf16.bf16.f32 " \
        "{%0,%1,%2,%3}, {%4,%5,%6,%7}, {%8,%9}, {%0,%1,%2,%3};" \
        : "+f"((C)[0]), "+f"((C)[1]), "+f"((C)[2]), "+f"((C)[3]) \
        : "r"((A)[0]), "r"((A)[1]), "r"((A)[2]), "r"((A)[3]), "r"(B0), "r"(B1))

__device__ __forceinline__ void split8(const float* v, __nv_bfloat16* hh, __nv_bfloat16* ll) {
    #pragma unroll
    for (int t = 0; t < 8; t++) {
        hh[t] = __float2bfloat16(v[t]);
        ll[t] = __float2bfloat16(v[t] - __bfloat162float(hh[t]));
    }
}

// ---------------- setup: weight split + zero counters (fused) ----------------
__global__ void k_wsetup(const float* __restrict__ W1, const float* __restrict__ W2,
                         const float* __restrict__ Wc1)
{
    int i = blockIdx.x*blockDim.x + threadIdx.x;
    if (i < RN) g_cnt[i] = 0;
    if (i >= 7*128*128) return;
    int slot = i >> 14, rem = i & 16383;
    int n = rem >> 7, k = rem & 127;
    float w;
    if (slot < 3)      w = W1[slot*16384 + k*128 + n];
    else if (slot < 6) w = W2[(slot-3)*16384 + k*128 + n];
    else               w = Wc1[k*128 + n];
    __nv_bfloat16 hi = __float2bfloat16(w);
    __nv_bfloat16 lo = __float2bfloat16(w - __bfloat162float(hi));
    g_wh[i] = hi;
    g_wl[i] = lo;
}

// ---------------- split feat -> g_xh/g_xl ----------------
__global__ void k_xsplit(const float* __restrict__ X) {
    int i = blockIdx.x*blockDim.x + threadIdx.x;   // one thread = 8 elements
    if (i >= NN*16) return;
    const float* xp = X + (size_t)i*8;
    float v[8];
    float4 a = *(const float4*)xp, b = *(const float4*)(xp+4);
    v[0]=a.x; v[1]=a.y; v[2]=a.z; v[3]=a.w; v[4]=b.x; v[5]=b.y; v[6]=b.z; v[7]=b.w;
    __nv_bfloat16 hh[8], ll[8];
    split8(v, hh, ll);
    *(uint4*)&g_xh[(size_t)i*8] = *(const uint4*)hh;
    *(uint4*)&g_xl[(size_t)i*8] = *(const uint4*)ll;
}

// ---------------- CSR build ----------------
__global__ void k_count(const int* __restrict__ edst) {
    int i = blockIdx.x*blockDim.x + threadIdx.x;
    if (i < RE) atomicAdd(&g_cnt[(i/EE)*NN + edst[i]], 1);
}
__device__ __forceinline__ int warp_incl_scan(int v) {
    int lane = threadIdx.x & 31;
    #pragma unroll
    for (int o = 1; o < 32; o <<= 1) {
        int t = __shfl_up_sync(0xffffffffu, v, o);
        if (lane >= o) v += t;
    }
    return v;
}
__global__ void k_scan_local() {
    __shared__ int ws[32];
    int i = blockIdx.x*1024 + threadIdx.x;
    int v = (i < RN) ? g_cnt[i] : 0;
    int incl = warp_incl_scan(v);
    int lane = threadIdx.x & 31, w = threadIdx.x >> 5;
    if (lane == 31) ws[w] = incl;
    __syncthreads();
    if (w == 0) { int b = ws[lane]; b = warp_incl_scan(b); ws[lane] = b; }
    __syncthreads();
    int off = (w > 0) ? ws[w-1] : 0;
    if (i < RN) g_off[i] = off + incl - v;
    if (threadIdx.x == 0) g_bsum[blockIdx.x] = ws[31];
}
__global__ void k_scan_bsum(int nb) {
    __shared__ int ws[8];
    int v = (threadIdx.x < nb) ? g_bsum[threadIdx.x] : 0;
    int incl = warp_incl_scan(v);
    int lane = threadIdx.x & 31, w = threadIdx.x >> 5;
    if (lane == 31) ws[w] = incl;
    __syncthreads();
    if (w == 0) { int b = (lane < 8) ? ws[lane] : 0; b = warp_incl_scan(b); if (lane < 8) ws[lane] = b; }
    __syncthreads();
    int off = (w > 0) ? ws[w-1] : 0;
    if (threadIdx.x < nb) g_bsum[threadIdx.x] = off + incl - v;
}
__global__ void k_scan_add() {
    int i = blockIdx.x*1024 + threadIdx.x;
    if (i < RN) {
        int o = g_off[i] + g_bsum[blockIdx.x];
        g_off[i] = o;
        g_cnt[i] = o;
    }
    if (i == 0) g_off[RN] = RE;
}
__global__ void k_fill(const int* __restrict__ esrc, const int* __restrict__ edst) {
    int i = blockIdx.x*blockDim.x + threadIdx.x;
    if (i < RE) {
        int idx = (i/EE)*NN + edst[i];
        int p = atomicAdd(&g_cnt[idx], 1);
        g_csr[p] = esrc[i];     // store src node id directly
    }
}

// ---------------- projection GEMM: 128x128 tile, per-relation grid ----------
// A pre-split bf16 in g_xh/g_xl. g_hp[r] (fp16), g_el/g_er from al/ar.
#define ASTR 72
#define SM_GEMM (4*128*ASTR*2 + 256*4 + 256*4)

__global__ void __launch_bounds__(256, 2)
k_proj(int slot0, const float* __restrict__ al, const float* __restrict__ ar)
{
    extern __shared__ char smem[];
    __nv_bfloat16* Ah = (__nv_bfloat16*)smem;       // [128][72]
    __nv_bfloat16* Av = Ah + 128*ASTR;
    __nv_bfloat16* Bh = Av + 128*ASTR;
    __nv_bfloat16* Bv = Bh + 128*ASTR;
    float* Ps = (float*)(Bv + 128*ASTR);

    const int tid  = threadIdx.x;
    const int lane = tid & 31;
    const int w    = tid >> 5;
    const int wm   = w & 3;
    const int wn   = w >> 2;
    const int r    = blockIdx.y;
    const int slot = slot0 + r;
    const int n0   = blockIdx.x * 128;

    Ps[tid] = (tid < 128) ? al[r*128 + tid] : ar[r*128 + tid - 128];

    const __nv_bfloat16* wh = g_wh + (size_t)slot*16384;
    const __nv_bfloat16* wl = g_wl + (size_t)slot*16384;

    const uint32_t sAh = smem_u32(Ah), sAv = smem_u32(Av);
    const uint32_t sBh = smem_u32(Bh), sBv = smem_u32(Bv);
    const uint32_t aOff = ((wm*32 + (lane & 15))*ASTR + (lane >> 4)*8) * 2;
    const uint32_t bOff = ((wn*64 + ((lane >> 4) & 1)*8 + (lane & 7))*ASTR
                           + ((lane >> 3) & 1)*8) * 2;

    float acc[2][8][4];
    #pragma unroll
    for (int mt = 0; mt < 2; mt++)
        #pragma unroll
        for (int nt = 0; nt < 8; nt++)
            #pragma unroll
            for (int q = 0; q < 4; q++) acc[mt][nt][q] = 0.f;

    #pragma unroll
    for (int ch = 0; ch < 2; ch++) {
        __syncthreads();
        #pragma unroll
        for (int i = 0; i < 4; i++) {
            int idx = tid + i*256;
            int n = idx >> 3, k = (idx & 7) << 3;
            *(uint4*)&Bh[n*ASTR + k] = *(const uint4*)&wh[n*128 + ch*64 + k];
            *(uint4*)&Bv[n*ASTR + k] = *(const uint4*)&wl[n*128 + ch*64 + k];
        }
        #pragma unroll
        for (int i = 0; i < 4; i++) {
            int idx = tid + i*256;
            int m = idx >> 3, k = (idx & 7) << 3;
            int gm = n0 + m;
            uint4 zh = make_uint4(0,0,0,0), zl = zh;
            if (gm < NN) {
                zh = *(const uint4*)&g_xh[(size_t)gm*128 + ch*64 + k];
                zl = *(const uint4*)&g_xl[(size_t)gm*128 + ch*64 + k];
            }
            *(uint4*)&Ah[m*ASTR + k] = zh;
            *(uint4*)&Av[m*ASTR + k] = zl;
        }
        __syncthreads();

        #pragma unroll
        for (int ks = 0; ks < 4; ks++) {
            uint32_t ah[2][4], av[2][4];
            #pragma unroll
            for (int mt = 0; mt < 2; mt++) {
                LDSM4(ah[mt], sAh + aOff + mt*(16*ASTR*2) + ks*32);
                LDSM4(av[mt], sAv + aOff + mt*(16*ASTR*2) + ks*32);
            }
            #pragma unroll
            for (int p = 0; p < 4; p++) {
                uint32_t bh[4], bv[4];
                LDSM4(bh, sBh + bOff + p*(16*ASTR*2) + ks*32);
                LDSM4(bv, sBv + bOff + p*(16*ASTR*2) + ks*32);
                #pragma unroll
                for (int mt = 0; mt < 2; mt++) {
                    MMA(acc[mt][2*p],   ah[mt], bh[0], bh[1]);
                    MMA(acc[mt][2*p],   ah[mt], bv[0], bv[1]);
                    MMA(acc[mt][2*p],   av[mt], bh[0], bh[1]);
                    MMA(acc[mt][2*p+1], ah[mt], bh[2], bh[3]);
                    MMA(acc[mt][2*p+1], ah[mt], bv[2], bv[3]);
                    MMA(acc[mt][2*p+1], av[mt], bh[2], bh[3]);
                }
            }
        }
    }

    const int g  = lane >> 2;
    const int c2 = (lane & 3) * 2;
    #pragma unroll
    for (int mt = 0; mt < 2; mt++) {
        #pragma unroll
        for (int rh = 0; rh < 2; rh++) {
            int gm = n0 + wm*32 + mt*16 + rh*8 + g;
            bool ok = gm < NN;
            if (ok) {
                __half* op = g_hp + ((size_t)r*NN + gm)*128;
                #pragma unroll
                for (int nt = 0; nt < 8; nt++) {
                    int n = wn*64 + nt*8 + c2;
                    *(__half2*)&op[n] =
                        __floats2half2_rn(acc[mt][nt][rh*2], acc[mt][nt][rh*2+1]);
                }
            }
            #pragma unroll
            for (int j = 0; j < 4; j++) {
                float el = 0.f, er = 0.f;
                #pragma unroll
                for (int t = 0; t < 2; t++) {
                    int nt = 2*j + t;
                    int n = wn*64 + nt*8 + c2;
                    float v0 = acc[mt][nt][rh*2], v1 = acc[mt][nt][rh*2+1];
                    el += v0*Ps[n] + v1*Ps[n+1];
                    er += v0*Ps[128+n] + v1*Ps[128+n+1];
                }
                el += __shfl_xor_sync(0xffffffffu, el, 1);
                er += __shfl_xor_sync(0xffffffffu, er, 1);
                el += __shfl_xor_sync(0xffffffffu, el, 2);
                er += __shfl_xor_sync(0xffffffffu, er, 2);
                if ((lane & 3) == 0 && ok) {
                    g_el[((size_t)r*NN + gm)*HH + wn*4 + j] = el;
                    g_er[((size_t)r*NN + gm)*HH + wn*4 + j] = er;
                }
            }
        }
    }
}

// ---------------- classifier GEMM (A from splits) ----------------
__global__ void __launch_bounds__(256, 2)
k_cls(const float* __restrict__ bc1, const float* __restrict__ wc2,
      const float* __restrict__ bc2, float* __restrict__ out1)
{
    extern __shared__ char smem[];
    __nv_bfloat16* Ah = (__nv_bfloat16*)smem;
    __nv_bfloat16* Av = Ah + 128*ASTR;
    __nv_bfloat16* Bh = Av + 128*ASTR;
    __nv_bfloat16* Bv = Bh + 128*ASTR;
    float* Ps = (float*)(Bv + 128*ASTR);
    float* Pt = Ps + 256;

    const int tid  = threadIdx.x;
    const int lane = tid & 31;
    const int w    = tid >> 5;
    const int wm   = w & 3;
    const int wn   = w >> 2;
    const int n0   = blockIdx.x * 128;

    Ps[tid] = (tid < 128) ? bc1[tid] : wc2[tid - 128];

    const __nv_bfloat16* wh = g_wh + (size_t)6*16384;
    const __nv_bfloat16* wl = g_wl + (size_t)6*16384;

    const uint32_t sAh = smem_u32(Ah), sAv = smem_u32(Av);
    const uint32_t sBh = smem_u32(Bh), sBv = smem_u32(Bv);
    const uint32_t aOff = ((wm*32 + (lane & 15))*ASTR + (lane >> 4)*8) * 2;
    const uint32_t bOff = ((wn*64 + ((lane >> 4) & 1)*8 + (lane & 7))*ASTR
                           + ((lane >> 3) & 1)*8) * 2;

    float acc[2][8][4];
    #pragma unroll
    for (int mt = 0; mt < 2; mt++)
        #pragma unroll
        for (int nt = 0; nt < 8; nt++)
            #pragma unroll
            for (int q = 0; q < 4; q++) acc[mt][nt][q] = 0.f;

    #pragma unroll
    for (int ch = 0; ch < 2; ch++) {
        __syncthreads();
        #pragma unroll
        for (int i = 0; i < 4; i++) {
            int idx = tid + i*256;
            int n = idx >> 3, k = (idx & 7) << 3;
            *(uint4*)&Bh[n*ASTR + k] = *(const uint4*)&wh[n*128 + ch*64 + k];
            *(uint4*)&Bv[n*ASTR + k] = *(const uint4*)&wl[n*128 + ch*64 + k];
        }
        #pragma unroll
        for (int i = 0; i < 4; i++) {
            int idx = tid + i*256;
            int m = idx >> 3, k = (idx & 7) << 3;
            int gm = n0 + m;
            uint4 zh = make_uint4(0,0,0,0), zl = zh;
            if (gm < NN) {
                zh = *(const uint4*)&g_xh[(size_t)gm*128 + ch*64 + k];
                zl = *(const uint4*)&g_xl[(size_t)gm*128 + ch*64 + k];
            }
            *(uint4*)&Ah[m*ASTR + k] = zh;
            *(uint4*)&Av[m*ASTR + k] = zl;
        }
        __syncthreads();

        #pragma unroll
        for (int ks = 0; ks < 4; ks++) {
            uint32_t ah[2][4], av[2][4];
            #pragma unroll
            for (int mt = 0; mt < 2; mt++) {
                LDSM4(ah[mt], sAh + aOff + mt*(16*ASTR*2) + ks*32);
                LDSM4(av[mt], sAv + aOff + mt*(16*ASTR*2) + ks*32);
            }
            #pragma unroll
            for (int p = 0; p < 4; p++) {
                uint32_t bh[4], bv[4];
                LDSM4(bh, sBh + bOff + p*(16*ASTR*2) + ks*32);
                LDSM4(bv, sBv + bOff + p*(16*ASTR*2) + ks*32);
                #pragma unroll
                for (int mt = 0; mt < 2; mt++) {
                    MMA(acc[mt][2*p],   ah[mt], bh[0], bh[1]);
                    MMA(acc[mt][2*p],   ah[mt], bv[0], bv[1]);
                    MMA(acc[mt][2*p],   av[mt], bh[0], bh[1]);
                    MMA(acc[mt][2*p+1], ah[mt], bh[2], bh[3]);
                    MMA(acc[mt][2*p+1], ah[mt], bv[2], bv[3]);
                    MMA(acc[mt][2*p+1], av[mt], bh[2], bh[3]);
                }
            }
        }
    }

    const int g  = lane >> 2;
    const int c2 = (lane & 3) * 2;
    #pragma unroll
    for (int mt = 0; mt < 2; mt++) {
        #pragma unroll
        for (int rh = 0; rh < 2; rh++) {
            float s = 0.f;
            #pragma unroll
            for (int nt = 0; nt < 8; nt++) {
                int n = wn*64 + nt*8 + c2;
                s += fmaxf(acc[mt][nt][rh*2]   + Ps[n],   0.f) * Ps[128+n];
                s += fmaxf(acc[mt][nt][rh*2+1] + Ps[n+1], 0.f) * Ps[128+n+1];
            }
            s += __shfl_xor_sync(0xffffffffu, s, 1);
            s += __shfl_xor_sync(0xffffffffu, s, 2);
            if ((lane & 3) == 0)
                Pt[(wm*32 + mt*16 + rh*8 + g)*2 + wn] = s;
        }
    }
    __syncthreads();
    if (tid < 128) {
        int gm = n0 + tid;
        if (gm < NN) out1[gm] = Pt[tid*2] + Pt[tid*2+1] + bc2[0];
    }
}

// ---------------- warp-per-node softmax-aggregate, unroll-4, split output ----
// mode 0: h1 = relu(agg+bias); writes g_h1 (fp32) + g_xh/g_xl (bf16 splits)
// mode 1: hn = LN(agg+bias+g_h1); writes g_xh/g_xl only (cls consumes splits)
__global__ void k_agg(const float* __restrict__ bias,
                      const float* __restrict__ lng, const float* __restrict__ lnb,
                      int mode)
{
    int warp = (blockIdx.x*blockDim.x + threadIdx.x) >> 5;
    if (warp >= NN) return;
    int v = warp;
    int lane = threadIdx.x & 31;
    int h = lane >> 2;

    float ax = 0.f, ay = 0.f, az = 0.f, aw = 0.f;

    #pragma unroll
    for (int r = 0; r < RR; r++) {
        int base = r*NN + v;
        int st = g_off[base], d = g_off[base+1] - st;
        if (d == 0) continue;
        float erv = __ldg(&g_er[(size_t)base*HH + h]);
        const __half* hpr = g_hp + (size_t)r*NN*DD;
        const float*  elr = g_el + (size_t)r*NN*HH;

        float nx = 0.f, ny = 0.f, nz = 0.f, nw = 0.f, den = 0.f;
        int i = 0;
        for (; i + 4 <= d; i += 4) {
            int s0 = __ldg(&g_csr[st+i]),   s1 = __ldg(&g_csr[st+i+1]);
            int s2 = __ldg(&g_csr[st+i+2]), s3 = __ldg(&g_csr[st+i+3]);
            float x0 = __ldg(&elr[(size_t)s0*HH + h]) + erv;
            float x1 = __ldg(&elr[(size_t)s1*HH + h]) + erv;
            float x2 = __ldg(&elr[(size_t)s2*HH + h]) + erv;
            float x3 = __ldg(&elr[(size_t)s3*HH + h]) + erv;
            uint2 u0 = *(const uint2*)&hpr[(size_t)s0*DD + lane*4];
            uint2 u1 = *(const uint2*)&hpr[(size_t)s1*DD + lane*4];
            uint2 u2 = *(const uint2*)&hpr[(size_t)s2*DD + lane*4];
            uint2 u3 = *(const uint2*)&hpr[(size_t)s3*DD + lane*4];
            x0 = x0 > 0.f ? x0 : NEG_SLOPE*x0;
            x1 = x1 > 0.f ? x1 : NEG_SLOPE*x1;
            x2 = x2 > 0.f ? x2 : NEG_SLOPE*x2;
            x3 = x3 > 0.f ? x3 : NEG_SLOPE*x3;
            float q0 = __expf(x0), q1 = __expf(x1), q2 = __expf(x2), q3 = __expf(x3);
            den += (q0 + q1) + (q2 + q3);
            float2 a0 = __half22float2(*(__half2*)&u0.x), b0 = __half22float2(*(__half2*)&u0.y);
            float2 a1 = __half22float2(*(__half2*)&u1.x), b1 = __half22float2(*(__half2*)&u1.y);
            float2 a2 = __half22float2(*(__half2*)&u2.x), b2 = __half22float2(*(__half2*)&u2.y);
            float2 a3 = __half22float2(*(__half2*)&u3.x), b3 = __half22float2(*(__half2*)&u3.y);
            nx += q0*a0.x + q1*a1.x + q2*a2.x + q3*a3.x;
            ny += q0*a0.y + q1*a1.y + q2*a2.y + q3*a3.y;
            nz += q0*b0.x + q1*b1.x + q2*b2.x + q3*b3.x;
            nw += q0*b0.y + q1*b1.y + q2*b2.y + q3*b3.y;
        }
        for (; i < d; i++) {
            int s0 = __ldg(&g_csr[st+i]);
            float x0 = __ldg(&elr[(size_t)s0*HH + h]) + erv;
            x0 = x0 > 0.f ? x0 : NEG_SLOPE*x0;
            float q0 = __expf(x0);
            den += q0;
            uint2 u0 = *(const uint2*)&hpr[(size_t)s0*DD + lane*4];
            float2 a0 = __half22float2(*(__half2*)&u0.x), b0 = __half22float2(*(__half2*)&u0.y);
            nx += q0*a0.x; ny += q0*a0.y; nz += q0*b0.x; nw += q0*b0.y;
        }
        float rd = 1.0f / den;
        ax += nx*rd; ay += ny*rd; az += nz*rd; aw += nw*rd;
    }

    int c = lane*4;
    ax += bias[c+0] + bias[128+c+0] + bias[256+c+0];
    ay += bias[c+1] + bias[128+c+1] + bias[256+c+1];
    az += bias[c+2] + bias[128+c+2] + bias[256+c+2];
    aw += bias[c+3] + bias[128+c+3] + bias[256+c+3];

    float o0, o1, o2, o3;
    if (mode == 0) {
        o0 = fmaxf(ax,0.f); o1 = fmaxf(ay,0.f); o2 = fmaxf(az,0.f); o3 = fmaxf(aw,0.f);
        *(float4*)&g_h1[(size_t)v*DD + c] = make_float4(o0, o1, o2, o3);
    } else {
        float4 hr = *(const float4*)&g_h1[(size_t)v*DD + c];
        ax += hr.x; ay += hr.y; az += hr.z; aw += hr.w;
        float s  = ax + ay + az + aw;
        float ss = ax*ax + ay*ay + az*az + aw*aw;
        #pragma unroll
        for (int o = 16; o; o >>= 1) {
            s  += __shfl_xor_sync(0xffffffffu, s,  o);
            ss += __shfl_xor_sync(0xffffffffu, ss, o);
        }
        float mu  = s * (1.0f/128.0f);
        float var = ss * (1.0f/128.0f) - mu*mu;
        float inv = rsqrtf(var + LN_EPS);
        o0 = (ax - mu)*inv*lng[c+0] + lnb[c+0];
        o1 = (ay - mu)*inv*lng[c+1] + lnb[c+1];
        o2 = (az - mu)*inv*lng[c+2] + lnb[c+2];
        o3 = (aw - mu)*inv*lng[c+3] + lnb[c+3];
    }
    // bf16 hi/lo split for the next GEMM
    float vv[4] = {o0, o1, o2, o3};
    __nv_bfloat16 hh[4], ll[4];
    #pragma unroll
    for (int t = 0; t < 4; t++) {
        hh[t] = __float2bfloat16(vv[t]);
        ll[t] = __float2bfloat16(vv[t] - __bfloat162float(hh[t]));
    }
    *(uint2*)&g_xh[(size_t)v*DD + c] = *(const uint2*)hh;
    *(uint2*)&g_xl[(size_t)v*DD + c] = *(const uint2*)ll;
}

// ---------------- launch ----------------
extern "C" void kernel_launch(void* const* d_in, const int* in_sizes, int n_in,
                              void* d_out, int out_size)
{
    const float* feat = (const float*)d_in[0];
    const int*   esrc = (const int*)d_in[1];
    const int*   edst = (const int*)d_in[2];
    const float* W1   = (const float*)d_in[3];
    const float* al1  = (const float*)d_in[4];
    const float* ar1  = (const float*)d_in[5];
    const float* b1   = (const float*)d_in[6];
    const float* W2   = (const float*)d_in[7];
    const float* al2  = (const float*)d_in[8];
    const float* ar2  = (const float*)d_in[9];
    const float* b2   = (const float*)d_in[10];
    const float* lng  = (const float*)d_in[11];
    const float* lnb  = (const float*)d_in[12];
    const float* Wc1  = (const float*)d_in[13];
    const float* bc1  = (const float*)d_in[14];
    const float* Wc2  = (const float*)d_in[15];
    const float* bc2  = (const float*)d_in[16];
    float* out = (float*)d_out;

    cudaFuncSetAttribute(k_proj, cudaFuncAttributeMaxDynamicSharedMemorySize, SM_GEMM);
    cudaFuncSetAttribute(k_cls,  cudaFuncAttributeMaxDynamicSharedMemorySize, SM_GEMM);

    const int NB = (RN + 1023) / 1024;
    int gx = (NN + 127)/128;
    dim3 gp(gx, RR);
    int aggBlocks = (NN*32 + 255)/256;

    // launch #4 is the layer-1 projection (for ncu capture)
    k_wsetup<<<(RN + 255)/256, 256>>>(W1, W2, Wc1);                        // 1
    k_count<<<(RE+255)/256, 256>>>(edst);                                  // 2
    k_xsplit<<<(NN*16 + 255)/256, 256>>>(feat);                            // 3
    k_proj<<<gp, 256, SM_GEMM>>>(0, al1, ar1);                             // 4  <-- profiled
    k_scan_local<<<NB, 1024>>>();                                          // 5
    k_scan_bsum<<<1, 256>>>(NB);                                           // 6
    k_scan_add<<<NB, 1024>>>();                                            // 7
    k_fill<<<(RE+255)/256, 256>>>(esrc, edst);                             // 8

    k_agg<<<aggBlocks, 256>>>(b1, nullptr, nullptr, 0);                    // 9
    k_proj<<<gp, 256, SM_GEMM>>>(3, al2, ar2);                             // 10
    k_agg<<<aggBlocks, 256>>>(b2, lng, lnb, 1);                            // 11
    k_cls<<<gx, 256, SM_GEMM>>>(bc1, Wc2, bc2, out);                       // 12
}

// round 9
// speedup vs baseline: 3.0221x; 1.0738x over previous
#include <cuda_runtime.h>
#include <cuda_bf16.h>
#include <cuda_fp16.h>
#include <cstdint>

#define NN 50000
#define EE 400000
#define RR 3
#define DD 128
#define HH 8
#define RN (RR*NN)
#define RE (RR*EE)
#define NEG_SLOPE 0.2f
#define LN_EPS 1e-5f

// ---------------- scratch (device globals; no allocs allowed) ----------------
__device__ __align__(128) __half g_hp[(size_t)RR*NN*DD];
__device__ __align__(128) float g_el[(size_t)RN*HH];
__device__ __align__(128) float g_er[(size_t)RN*HH];
__device__ __align__(128) float g_h1[(size_t)NN*DD];
__device__ __align__(128) __nv_bfloat16 g_xh[(size_t)NN*DD];
__device__ __align__(128) __nv_bfloat16 g_xl[(size_t)NN*DD];
__device__ __align__(128) int   g_off[RN+1];
__device__ __align__(128) int   g_cnt[RN];
__device__ __align__(128) int   g_csr[RE];      // src node ids
__device__ __align__(128) int   g_bsum[256];
// pre-built B mma fragments: [slot(7)][ks(8)][n16(8)][split(2)][lane(32)][reg(4)]
__device__ __align__(128) uint32_t g_wf[7*8*8*2*32*4];

__device__ __forceinline__ uint32_t smem_u32(const void* p) {
    uint32_t a;
    asm("{ .reg .u64 t; cvta.to.shared.u64 t, %1; cvt.u32.u64 %0, t; }" : "=r"(a) : "l"(p));
    return a;
}

#define LDSM4(R, A) \
    asm volatile("ldmatrix.sync.aligned.m8n8.x4.shared.b16 {%0,%1,%2,%3}, [%4];" \
        : "=r"((R)[0]), "=r"((R)[1]), "=r"((R)[2]), "=r"((R)[3]) : "r"(A))

#define MMA(C, A, B0, B1) \
    asm volatile("mma.sync.aligned.m16n8k16.row.col.f32.bf16.bf16.f32 " \
        "{%0,%1,%2,%3}, {%4,%5,%6,%7}, {%8,%9}, {%0,%1,%2,%3};" \
        : "+f"((C)[0]), "+f"((C)[1]), "+f"((C)[2]), "+f"((C)[3]) \
        : "r"((A)[0]), "r"((A)[1]), "r"((A)[2]), "r"((A)[3]), "r"(B0), "r"(B1))

__device__ __forceinline__ uint32_t pack_bf16(__nv_bfloat16 a, __nv_bfloat16 b) {
    uint16_t lo = *(uint16_t*)&a, hi = *(uint16_t*)&b;
    return (uint32_t)lo | ((uint32_t)hi << 16);
}

// ---------------- setup: cnt zero + weight fragments + feat split ------------
__global__ void k_setup(const float* __restrict__ W1, const float* __restrict__ W2,
                        const float* __restrict__ Wc1, const float* __restrict__ X)
{
    int i = blockIdx.x*blockDim.x + threadIdx.x;
    if (i < RN) g_cnt[i] = 0;

    // weight fragment build: one thread per (slot, ks, n16, lane), both splits
    if (i < 7*8*8*32) {
        int lane = i & 31;
        int rem  = i >> 5;
        int p16  = rem & 7;  rem >>= 3;
        int ks   = rem & 7;  rem >>= 3;
        int slot = rem;
        const float* Wsrc = (slot < 3) ? W1 + (size_t)slot*16384
                          : (slot < 6) ? W2 + (size_t)(slot-3)*16384
                          : Wc1;
        uint32_t fh[4], fl[4];
        #pragma unroll
        for (int j = 0; j < 4; j++) {
            int n = p16*16 + (j>>1)*8 + (lane>>2);
            int k = ks*16  + (j&1)*8  + (lane&3)*2;
            float w0 = Wsrc[(size_t)k*128 + n];
            float w1 = Wsrc[(size_t)(k+1)*128 + n];
            __nv_bfloat16 h0 = __float2bfloat16(w0);
            __nv_bfloat16 h1 = __float2bfloat16(w1);
            __nv_bfloat16 l0 = __float2bfloat16(w0 - __bfloat162float(h0));
            __nv_bfloat16 l1 = __float2bfloat16(w1 - __bfloat162float(h1));
            fh[j] = pack_bf16(h0, h1);
            fl[j] = pack_bf16(l0, l1);
        }
        size_t base = ((((size_t)slot*8 + ks)*8 + p16)*2)*128 + (size_t)lane*4;
        *(uint4*)&g_wf[base]       = make_uint4(fh[0], fh[1], fh[2], fh[3]);
        *(uint4*)&g_wf[base + 128] = make_uint4(fl[0], fl[1], fl[2], fl[3]);
    }

    // feat split: one thread per 8 elements
    if (i < NN*16) {
        const float* xp = X + (size_t)i*8;
        float4 a = *(const float4*)xp, b = *(const float4*)(xp+4);
        float v[8] = {a.x,a.y,a.z,a.w,b.x,b.y,b.z,b.w};
        __nv_bfloat16 hh[8], ll[8];
        #pragma unroll
        for (int t = 0; t < 8; t++) {
            hh[t] = __float2bfloat16(v[t]);
            ll[t] = __float2bfloat16(v[t] - __bfloat162float(hh[t]));
        }
        *(uint4*)&g_xh[(size_t)i*8] = *(const uint4*)hh;
        *(uint4*)&g_xl[(size_t)i*8] = *(const uint4*)ll;
    }
}

// ---------------- CSR build ----------------
__global__ void k_count(const int* __restrict__ edst) {
    int i = blockIdx.x*blockDim.x + threadIdx.x;
    if (i < RE) atomicAdd(&g_cnt[(i/EE)*NN + edst[i]], 1);
}
__device__ __forceinline__ int warp_incl_scan(int v) {
    int lane = threadIdx.x & 31;
    #pragma unroll
    for (int o = 1; o < 32; o <<= 1) {
        int t = __shfl_up_sync(0xffffffffu, v, o);
        if (lane >= o) v += t;
    }
    return v;
}
__global__ void k_scan_local() {
    __shared__ int ws[32];
    int i = blockIdx.x*1024 + threadIdx.x;
    int v = (i < RN) ? g_cnt[i] : 0;
    int incl = warp_incl_scan(v);
    int lane = threadIdx.x & 31, w = threadIdx.x >> 5;
    if (lane == 31) ws[w] = incl;
    __syncthreads();
    if (w == 0) { int b = ws[lane]; b = warp_incl_scan(b); ws[lane] = b; }
    __syncthreads();
    int off = (w > 0) ? ws[w-1] : 0;
    if (i < RN) g_off[i] = off + incl - v;
    if (threadIdx.x == 0) g_bsum[blockIdx.x] = ws[31];
}
__global__ void k_scan_bsum(int nb) {
    __shared__ int ws[8];
    int v = (threadIdx.x < nb) ? g_bsum[threadIdx.x] : 0;
    int incl = warp_incl_scan(v);
    int lane = threadIdx.x & 31, w = threadIdx.x >> 5;
    if (lane == 31) ws[w] = incl;
    __syncthreads();
    if (w == 0) { int b = (lane < 8) ? ws[lane] : 0; b = warp_incl_scan(b); if (lane < 8) ws[lane] = b; }
    __syncthreads();
    int off = (w > 0) ? ws[w-1] : 0;
    if (threadIdx.x < nb) g_bsum[threadIdx.x] = off + incl - v;
}
__global__ void k_scan_add() {
    int i = blockIdx.x*1024 + threadIdx.x;
    if (i < RN) {
        int o = g_off[i] + g_bsum[blockIdx.x];
        g_off[i] = o;
        g_cnt[i] = o;
    }
    if (i == 0) g_off[RN] = RE;
}
__global__ void k_fill(const int* __restrict__ esrc, const int* __restrict__ edst) {
    int i = blockIdx.x*blockDim.x + threadIdx.x;
    if (i < RE) {
        int idx = (i/EE)*NN + edst[i];
        int p = atomicAdd(&g_cnt[idx], 1);
        g_csr[p] = esrc[i];
    }
}

// ---------------- projection GEMM: A smem full-K, B direct-LDG fragments ----
#define ASTRA 136
#define SM_PROJ (2*128*ASTRA*2 + 1024)
#define SM_CLS  (2*128*ASTRA*2 + 2048)

__global__ void __launch_bounds__(256, 2)
k_proj(int slot0, const float* __restrict__ al, const float* __restrict__ ar)
{
    extern __shared__ char smem[];
    __nv_bfloat16* Ah = (__nv_bfloat16*)smem;       // [128][136]
    __nv_bfloat16* Av = Ah + 128*ASTRA;
    float* Ps = (float*)(Av + 128*ASTRA);

    const int tid  = threadIdx.x;
    const int lane = tid & 31;
    const int w    = tid >> 5;
    const int wm   = w & 3;
    const int wn   = w >> 2;
    const int r    = blockIdx.y;
    const int slot = slot0 + r;
    const int n0   = blockIdx.x * 128;

    Ps[tid] = (tid < 128) ? al[r*128 + tid] : ar[r*128 + tid - 128];

    // stage A (full K), pre-split bf16
    #pragma unroll
    for (int i = 0; i < 8; i++) {
        int idx = tid + i*256;
        int m = idx >> 4, k = (idx & 15) << 3;
        int gm = n0 + m;
        uint4 zh = make_uint4(0,0,0,0), zl = zh;
        if (gm < NN) {
            zh = *(const uint4*)&g_xh[(size_t)gm*128 + k];
            zl = *(const uint4*)&g_xl[(size_t)gm*128 + k];
        }
        *(uint4*)&Ah[m*ASTRA + k] = zh;
        *(uint4*)&Av[m*ASTRA + k] = zl;
    }
    __syncthreads();

    const uint32_t sAh = smem_u32(Ah), sAv = smem_u32(Av);
    const uint32_t aOff = ((wm*32 + (lane & 15))*ASTRA + (lane >> 4)*8) * 2;
    const uint32_t* wf = g_wf + (size_t)slot*8*8*2*128;

    float acc[2][8][4];
    #pragma unroll
    for (int mt = 0; mt < 2; mt++)
        #pragma unroll
        for (int nt = 0; nt < 8; nt++)
            #pragma unroll
            for (int q = 0; q < 4; q++) acc[mt][nt][q] = 0.f;

    #pragma unroll 2
    for (int ks = 0; ks < 8; ks++) {
        uint32_t ah[2][4], av[2][4];
        #pragma unroll
        for (int mt = 0; mt < 2; mt++) {
            LDSM4(ah[mt], sAh + aOff + mt*(16*ASTRA*2) + ks*32);
            LDSM4(av[mt], sAv + aOff + mt*(16*ASTRA*2) + ks*32);
        }
        #pragma unroll
        for (int p = 0; p < 4; p++) {
            int p16 = wn*4 + p;
            const uint4* bp = (const uint4*)(wf + ((ks*8 + p16)*2)*128) + lane;
            uint4 h4 = __ldg(bp);
            uint4 l4 = __ldg(bp + 32);           // split stride 128 u32 = 32 uint4
            uint32_t bh[4] = {h4.x, h4.y, h4.z, h4.w};
            uint32_t bv[4] = {l4.x, l4.y, l4.z, l4.w};
            #pragma unroll
            for (int mt = 0; mt < 2; mt++) {
                MMA(acc[mt][2*p],   ah[mt], bh[0], bh[1]);
                MMA(acc[mt][2*p],   ah[mt], bv[0], bv[1]);
                MMA(acc[mt][2*p],   av[mt], bh[0], bh[1]);
                MMA(acc[mt][2*p+1], ah[mt], bh[2], bh[3]);
                MMA(acc[mt][2*p+1], ah[mt], bv[2], bv[3]);
                MMA(acc[mt][2*p+1], av[mt], bh[2], bh[3]);
            }
        }
    }

    const int g  = lane >> 2;
    const int c2 = (lane & 3) * 2;
    #pragma unroll
    for (int mt = 0; mt < 2; mt++) {
        #pragma unroll
        for (int rh = 0; rh < 2; rh++) {
            int gm = n0 + wm*32 + mt*16 + rh*8 + g;
            bool ok = gm < NN;
            if (ok) {
                __half* op = g_hp + ((size_t)r*NN + gm)*128;
                #pragma unroll
                for (int nt = 0; nt < 8; nt++) {
                    int n = wn*64 + nt*8 + c2;
                    *(__half2*)&op[n] =
                        __floats2half2_rn(acc[mt][nt][rh*2], acc[mt][nt][rh*2+1]);
                }
            }
            #pragma unroll
            for (int j = 0; j < 4; j++) {
                float el = 0.f, er = 0.f;
                #pragma unroll
                for (int t = 0; t < 2; t++) {
                    int nt = 2*j + t;
                    int n = wn*64 + nt*8 + c2;
                    float v0 = acc[mt][nt][rh*2], v1 = acc[mt][nt][rh*2+1];
                    el += v0*Ps[n] + v1*Ps[n+1];
                    er += v0*Ps[128+n] + v1*Ps[128+n+1];
                }
                el += __shfl_xor_sync(0xffffffffu, el, 1);
                er += __shfl_xor_sync(0xffffffffu, er, 1);
                el += __shfl_xor_sync(0xffffffffu, el, 2);
                er += __shfl_xor_sync(0xffffffffu, er, 2);
                if ((lane & 3) == 0 && ok) {
                    g_el[((size_t)r*NN + gm)*HH + wn*4 + j] = el;
                    g_er[((size_t)r*NN + gm)*HH + wn*4 + j] = er;
                }
            }
        }
    }
}

// ---------------- classifier GEMM ----------------
__global__ void __launch_bounds__(256, 2)
k_cls(const float* __restrict__ bc1, const float* __restrict__ wc2,
      const float* __restrict__ bc2, float* __restrict__ out1)
{
    extern __shared__ char smem[];
    __nv_bfloat16* Ah = (__nv_bfloat16*)smem;
    __nv_bfloat16* Av = Ah + 128*ASTRA;
    float* Ps = (float*)(Av + 128*ASTRA);
    float* Pt = Ps + 256;

    const int tid  = threadIdx.x;
    const int lane = tid & 31;
    const int w    = tid >> 5;
    const int wm   = w & 3;
    const int wn   = w >> 2;
    const int n0   = blockIdx.x * 128;

    Ps[tid] = (tid < 128) ? bc1[tid] : wc2[tid - 128];

    #pragma unroll
    for (int i = 0; i < 8; i++) {
        int idx = tid + i*256;
        int m = idx >> 4, k = (idx & 15) << 3;
        int gm = n0 + m;
        uint4 zh = make_uint4(0,0,0,0), zl = zh;
        if (gm < NN) {
            zh = *(const uint4*)&g_xh[(size_t)gm*128 + k];
            zl = *(const uint4*)&g_xl[(size_t)gm*128 + k];
        }
        *(uint4*)&Ah[m*ASTRA + k] = zh;
        *(uint4*)&Av[m*ASTRA + k] = zl;
    }
    __syncthreads();

    const uint32_t sAh = smem_u32(Ah), sAv = smem_u32(Av);
    const uint32_t aOff = ((wm*32 + (lane & 15))*ASTRA + (lane >> 4)*8) * 2;
    const uint32_t* wf = g_wf + (size_t)6*8*8*2*128;

    float acc[2][8][4];
    #pragma unroll
    for (int mt = 0; mt < 2; mt++)
        #pragma unroll
        for (int nt = 0; nt < 8; nt++)
            #pragma unroll
            for (int q = 0; q < 4; q++) acc[mt][nt][q] = 0.f;

    #pragma unroll 2
    for (int ks = 0; ks < 8; ks++) {
        uint32_t ah[2][4], av[2][4];
        #pragma unroll
        for (int mt = 0; mt < 2; mt++) {
            LDSM4(ah[mt], sAh + aOff + mt*(16*ASTRA*2) + ks*32);
            LDSM4(av[mt], sAv + aOff + mt*(16*ASTRA*2) + ks*32);
        }
        #pragma unroll
        for (int p = 0; p < 4; p++) {
            int p16 = wn*4 + p;
            const uint4* bp = (const uint4*)(wf + ((ks*8 + p16)*2)*128) + lane;
            uint4 h4 = __ldg(bp);
            uint4 l4 = __ldg(bp + 32);
            uint32_t bh[4] = {h4.x, h4.y, h4.z, h4.w};
            uint32_t bv[4] = {l4.x, l4.y, l4.z, l4.w};
            #pragma unroll
            for (int mt = 0; mt < 2; mt++) {
                MMA(acc[mt][2*p],   ah[mt], bh[0], bh[1]);
                MMA(acc[mt][2*p],   ah[mt], bv[0], bv[1]);
                MMA(acc[mt][2*p],   av[mt], bh[0], bh[1]);
                MMA(acc[mt][2*p+1], ah[mt], bh[2], bh[3]);
                MMA(acc[mt][2*p+1], ah[mt], bv[2], bv[3]);
                MMA(acc[mt][2*p+1], av[mt], bh[2], bh[3]);
            }
        }
    }

    const int g  = lane >> 2;
    const int c2 = (lane & 3) * 2;
    #pragma unroll
    for (int mt = 0; mt < 2; mt++) {
        #pragma unroll
        for (int rh = 0; rh < 2; rh++) {
            float s = 0.f;
            #pragma unroll
            for (int nt = 0; nt < 8; nt++) {
                int n = wn*64 + nt*8 + c2;
                s += fmaxf(acc[mt][nt][rh*2]   + Ps[n],   0.f) * Ps[128+n];
                s += fmaxf(acc[mt][nt][rh*2+1] + Ps[n+1], 0.f) * Ps[128+n+1];
            }
            s += __shfl_xor_sync(0xffffffffu, s, 1);
            s += __shfl_xor_sync(0xffffffffu, s, 2);
            if ((lane & 3) == 0)
                Pt[(wm*32 + mt*16 + rh*8 + g)*2 + wn] = s;
        }
    }
    __syncthreads();
    if (tid < 128) {
        int gm = n0 + tid;
        if (gm < NN) out1[gm] = Pt[tid*2] + Pt[tid*2+1] + bc2[0];
    }
}

// ---------------- warp-per-node softmax-aggregate, unroll-4 ------------------
__global__ void k_agg(const float* __restrict__ bias,
                      const float* __restrict__ lng, const float* __restrict__ lnb,
                      int mode)
{
    int warp = (blockIdx.x*blockDim.x + threadIdx.x) >> 5;
    if (warp >= NN) return;
    int v = warp;
    int lane = threadIdx.x & 31;
    int h = lane >> 2;

    float ax = 0.f, ay = 0.f, az = 0.f, aw = 0.f;

    #pragma unroll
    for (int r = 0; r < RR; r++) {
        int base = r*NN + v;
        int st = g_off[base], d = g_off[base+1] - st;
        if (d == 0) continue;
        float erv = __ldg(&g_er[(size_t)base*HH + h]);
        const __half* hpr = g_hp + (size_t)r*NN*DD;
        const float*  elr = g_el + (size_t)r*NN*HH;

        float nx = 0.f, ny = 0.f, nz = 0.f, nw = 0.f, den = 0.f;
        int i = 0;
        for (; i + 4 <= d; i += 4) {
            int s0 = __ldg(&g_csr[st+i]),   s1 = __ldg(&g_csr[st+i+1]);
            int s2 = __ldg(&g_csr[st+i+2]), s3 = __ldg(&g_csr[st+i+3]);
            float x0 = __ldg(&elr[(size_t)s0*HH + h]) + erv;
            float x1 = __ldg(&elr[(size_t)s1*HH + h]) + erv;
            float x2 = __ldg(&elr[(size_t)s2*HH + h]) + erv;
            float x3 = __ldg(&elr[(size_t)s3*HH + h]) + erv;
            uint2 u0 = *(const uint2*)&hpr[(size_t)s0*DD + lane*4];
            uint2 u1 = *(const uint2*)&hpr[(size_t)s1*DD + lane*4];
            uint2 u2 = *(const uint2*)&hpr[(size_t)s2*DD + lane*4];
            uint2 u3 = *(const uint2*)&hpr[(size_t)s3*DD + lane*4];
            x0 = x0 > 0.f ? x0 : NEG_SLOPE*x0;
            x1 = x1 > 0.f ? x1 : NEG_SLOPE*x1;
            x2 = x2 > 0.f ? x2 : NEG_SLOPE*x2;
            x3 = x3 > 0.f ? x3 : NEG_SLOPE*x3;
            float q0 = __expf(x0), q1 = __expf(x1), q2 = __expf(x2), q3 = __expf(x3);
            den += (q0 + q1) + (q2 + q3);
            float2 a0 = __half22float2(*(__half2*)&u0.x), b0 = __half22float2(*(__half2*)&u0.y);
            float2 a1 = __half22float2(*(__half2*)&u1.x), b1 = __half22float2(*(__half2*)&u1.y);
            float2 a2 = __half22float2(*(__half2*)&u2.x), b2 = __half22float2(*(__half2*)&u2.y);
            float2 a3 = __half22float2(*(__half2*)&u3.x), b3 = __half22float2(*(__half2*)&u3.y);
            nx += q0*a0.x + q1*a1.x + q2*a2.x + q3*a3.x;
            ny += q0*a0.y + q1*a1.y + q2*a2.y + q3*a3.y;
            nz += q0*b0.x + q1*b1.x + q2*b2.x + q3*b3.x;
            nw += q0*b0.y + q1*b1.y + q2*b2.y + q3*b3.y;
        }
        for (; i < d; i++) {
            int s0 = __ldg(&g_csr[st+i]);
            float x0 = __ldg(&elr[(size_t)s0*HH + h]) + erv;
            x0 = x0 > 0.f ? x0 : NEG_SLOPE*x0;
            float q0 = __expf(x0);
            den += q0;
            uint2 u0 = *(const uint2*)&hpr[(size_t)s0*DD + lane*4];
            float2 a0 = __half22float2(*(__half2*)&u0.x), b0 = __half22float2(*(__half2*)&u0.y);
            nx += q0*a0.x; ny += q0*a0.y; nz += q0*b0.x; nw += q0*b0.y;
        }
        float rd = 1.0f / den;
        ax += nx*rd; ay += ny*rd; az += nz*rd; aw += nw*rd;
    }

    int c = lane*4;
    ax += bias[c+0] + bias[128+c+0] + bias[256+c+0];
    ay += bias[c+1] + bias[128+c+1] + bias[256+c+1];
    az += bias[c+2] + bias[128+c+2] + bias[256+c+2];
    aw += bias[c+3] + bias[128+c+3] + bias[256+c+3];

    float o0, o1, o2, o3;
    if (mode == 0) {
        o0 = fmaxf(ax,0.f); o1 = fmaxf(ay,0.f); o2 = fmaxf(az,0.f); o3 = fmaxf(aw,0.f);
        *(float4*)&g_h1[(size_t)v*DD + c] = make_float4(o0, o1, o2, o3);
    } else {
        float4 hr = *(const float4*)&g_h1[(size_t)v*DD + c];
        ax += hr.x; ay += hr.y; az += hr.z; aw += hr.w;
        float s  = ax + ay + az + aw;
        float ss = ax*ax + ay*ay + az*az + aw*aw;
        #pragma unroll
        for (int o = 16; o; o >>= 1) {
            s  += __shfl_xor_sync(0xffffffffu, s,  o);
            ss += __shfl_xor_sync(0xffffffffu, ss, o);
        }
        float mu  = s * (1.0f/128.0f);
        float var = ss * (1.0f/128.0f) - mu*mu;
        float inv = rsqrtf(var + LN_EPS);
        o0 = (ax - mu)*inv*lng[c+0] + lnb[c+0];
        o1 = (ay - mu)*inv*lng[c+1] + lnb[c+1];
        o2 = (az - mu)*inv*lng[c+2] + lnb[c+2];
        o3 = (aw - mu)*inv*lng[c+3] + lnb[c+3];
    }
    float vv[4] = {o0, o1, o2, o3};
    __nv_bfloat16 hh[4], ll[4];
    #pragma unroll
    for (int t = 0; t < 4; t++) {
        hh[t] = __float2bfloat16(vv[t]);
        ll[t] = __float2bfloat16(vv[t] - __bfloat162float(hh[t]));
    }
    *(uint2*)&g_xh[(size_t)v*DD + c] = *(const uint2*)hh;
    *(uint2*)&g_xl[(size_t)v*DD + c] = *(const uint2*)ll;
}

// ---------------- launch ----------------
extern "C" void kernel_launch(void* const* d_in, const int* in_sizes, int n_in,
                              void* d_out, int out_size)
{
    const float* feat = (const float*)d_in[0];
    const int*   esrc = (const int*)d_in[1];
    const int*   edst = (const int*)d_in[2];
    const float* W1   = (const float*)d_in[3];
    const float* al1  = (const float*)d_in[4];
    const float* ar1  = (const float*)d_in[5];
    const float* b1   = (const float*)d_in[6];
    const float* W2   = (const float*)d_in[7];
    const float* al2  = (const float*)d_in[8];
    const float* ar2  = (const float*)d_in[9];
    const float* b2   = (const float*)d_in[10];
    const float* lng  = (const float*)d_in[11];
    const float* lnb  = (const float*)d_in[12];
    const float* Wc1  = (const float*)d_in[13];
    const float* bc1  = (const float*)d_in[14];
    const float* Wc2  = (const float*)d_in[15];
    const float* bc2  = (const float*)d_in[16];
    float* out = (float*)d_out;

    cudaFuncSetAttribute(k_proj, cudaFuncAttributeMaxDynamicSharedMemorySize, SM_PROJ);
    cudaFuncSetAttribute(k_cls,  cudaFuncAttributeMaxDynamicSharedMemorySize, SM_CLS);

    const int NB = (RN + 1023) / 1024;
    int gx = (NN + 127)/128;
    dim3 gp(gx, RR);
    int aggBlocks = (NN*32 + 255)/256;

    // launch #4 is the layer-1 projection (for ncu capture)
    k_setup<<<(NN*16 + 255)/256, 256>>>(W1, W2, Wc1, feat);                // 1
    k_count<<<(RE+255)/256, 256>>>(edst);                                  // 2
    k_scan_local<<<NB, 1024>>>();                                          // 3
    k_proj<<<gp, 256, SM_PROJ>>>(0, al1, ar1);                             // 4  <-- profiled
    k_scan_bsum<<<1, 256>>>(NB);                                           // 5
    k_scan_add<<<NB, 1024>>>();                                            // 6
    k_fill<<<(RE+255)/256, 256>>>(esrc, edst);                             // 7

    k_agg<<<aggBlocks, 256>>>(b1, nullptr, nullptr, 0);                    // 8
    k_proj<<<gp, 256, SM_PROJ>>>(3, al2, ar2);                             // 9
    k_agg<<<aggBlocks, 256>>>(b2, lng, lnb, 1);                            // 10
    k_cls<<<gx, 256, SM_CLS>>>(bc1, Wc2, bc2, out);                        // 11
}